// round 2
// baseline (speedup 1.0000x reference)
#include <cuda_runtime.h>
#include <math.h>

// Problem constants: B=2, T=2048, D=1024, H=16, hd=64, M = B*T = 4096
#define MROWS 4096

// ---------------- scratch (device globals; no allocation allowed) ----------
__device__ float g_tpu[2 * 2048];        // time MLP hidden
__device__ float g_tps[2 * 1024];        // time MLP after swiglu
__device__ float g_tp [2 * 4096];        // shift1|scale1|shift2|scale2
__device__ float g_h  [MROWS * 1024];    // normed/modulated activations
__device__ float g_qkv[MROWS * 3072];    // qkv projections
__device__ float g_att[MROWS * 1024];    // attention output (b,t,h,d)
__device__ float g_x1 [MROWS * 1024];    // x after attention residual
__device__ float g_u  [MROWS * 8192];    // ffn pre-activation
__device__ float g_sw [MROWS * 4096];    // ffn post-swiglu

// ---------------- tiny time-MLP GEMMs (M=2) --------------------------------
__global__ void k_smallmm(const float* __restrict__ in, const float* __restrict__ w,
                          const float* __restrict__ bias, float* __restrict__ out,
                          int K, int N) {
    int n = blockIdx.x * 256 + threadIdx.x;
    int b = blockIdx.y;
    if (n >= N) return;
    float acc = bias[n];
    const float* xr = in + b * K;
    #pragma unroll 8
    for (int k = 0; k < K; ++k) acc += xr[k] * w[k * N + n];
    out[b * N + n] = acc;
}

__global__ void k_tswiglu(const float* __restrict__ u, float* __restrict__ s) {
    int i = blockIdx.x * 256 + threadIdx.x;  // 2048 total
    if (i >= 2048) return;
    int b = i >> 10, j = i & 1023;
    float a = u[b * 2048 + j];
    float g = u[b * 2048 + 1024 + j];
    s[b * 1024 + j] = a * (g / (1.f + expf(-g)));
}

// ---------------- fused RMSNorm + adaLN modulation --------------------------
__global__ __launch_bounds__(256) void k_rmsnorm(const float* __restrict__ x,
                                                 const float* __restrict__ g,
                                                 const float* __restrict__ tp,
                                                 int shift_off, int scale_off,
                                                 float* __restrict__ out) {
    int row = blockIdx.x;          // 0..4095
    int b   = row >> 11;
    const float4* xr = (const float4*)(x + row * 1024);
    float4 v = xr[threadIdx.x];    // 256 threads * 4 = 1024
    float ss = v.x * v.x + v.y * v.y + v.z * v.z + v.w * v.w;
    #pragma unroll
    for (int off = 16; off; off >>= 1) ss += __shfl_xor_sync(0xFFFFFFFFu, ss, off);
    __shared__ float wsum[8];
    __shared__ float stot;
    if ((threadIdx.x & 31) == 0) wsum[threadIdx.x >> 5] = ss;
    __syncthreads();
    if (threadIdx.x == 0) {
        float t = 0.f;
        #pragma unroll
        for (int i = 0; i < 8; ++i) t += wsum[i];
        stot = rsqrtf(t * (1.f / 1024.f) + 1.1920928955078125e-7f);
    }
    __syncthreads();
    float r = stot;
    int j = threadIdx.x * 4;
    const float* gg = g + j;
    const float* sc = tp + b * 4096 + scale_off + j;
    const float* sh = tp + b * 4096 + shift_off + j;
    float4 o;
    o.x = v.x * r * gg[0] * (1.f + sc[0]) + sh[0];
    o.y = v.y * r * gg[1] * (1.f + sc[1]) + sh[1];
    o.z = v.z * r * gg[2] * (1.f + sc[2]) + sh[2];
    o.w = v.w * r * gg[3] * (1.f + sc[3]) + sh[3];
    ((float4*)(out + row * 1024))[threadIdx.x] = o;
}

// ---------------- 128x128x8 register-blocked SGEMM (bias + opt residual) ----
template <bool RES>
__global__ __launch_bounds__(256) void k_sgemm(const float* __restrict__ A,
                                               const float* __restrict__ B,
                                               const float* __restrict__ bias,
                                               const float* __restrict__ res,
                                               float* __restrict__ C,
                                               int Nn, int Kn) {
    __shared__ float As[8][128];
    __shared__ float Bs[8][128];
    const int tid = threadIdx.x;
    const int tx = tid & 15, ty = tid >> 4;
    const int arow = tid >> 1, acol = (tid & 1) * 4;
    const int brow = tid >> 5, bcol = (tid & 31) * 4;
    const float* Ap = A + (blockIdx.y * 128 + arow) * Kn + acol;
    const float* Bp = B + brow * Nn + blockIdx.x * 128 + bcol;

    float acc[8][8];
    #pragma unroll
    for (int i = 0; i < 8; ++i)
        #pragma unroll
        for (int j = 0; j < 8; ++j) acc[i][j] = 0.f;

    for (int k0 = 0; k0 < Kn; k0 += 8) {
        float4 a4 = *(const float4*)Ap;  Ap += 8;
        float4 b4 = *(const float4*)Bp;  Bp += 8 * Nn;
        As[acol + 0][arow] = a4.x;
        As[acol + 1][arow] = a4.y;
        As[acol + 2][arow] = a4.z;
        As[acol + 3][arow] = a4.w;
        *(float4*)&Bs[brow][bcol] = b4;
        __syncthreads();
        #pragma unroll
        for (int k = 0; k < 8; ++k) {
            float a[8], bb[8];
            *(float4*)(a)      = *(const float4*)&As[k][ty * 4];
            *(float4*)(a + 4)  = *(const float4*)&As[k][64 + ty * 4];
            *(float4*)(bb)     = *(const float4*)&Bs[k][tx * 4];
            *(float4*)(bb + 4) = *(const float4*)&Bs[k][64 + tx * 4];
            #pragma unroll
            for (int i = 0; i < 8; ++i)
                #pragma unroll
                for (int j = 0; j < 8; ++j) acc[i][j] += a[i] * bb[j];
        }
        __syncthreads();
    }

    const int row0 = blockIdx.y * 128, col0 = blockIdx.x * 128;
    #pragma unroll
    for (int i = 0; i < 8; ++i) {
        int r = row0 + ty * 4 + (i & 3) + ((i >= 4) ? 64 : 0);
        #pragma unroll
        for (int jh = 0; jh < 2; ++jh) {
            int c = col0 + tx * 4 + jh * 64;
            float4 w;
            w.x = acc[i][jh * 4 + 0] + bias[c + 0];
            w.y = acc[i][jh * 4 + 1] + bias[c + 1];
            w.z = acc[i][jh * 4 + 2] + bias[c + 2];
            w.w = acc[i][jh * 4 + 3] + bias[c + 3];
            if (RES) {
                const float4 rv = *(const float4*)(res + (size_t)r * Nn + c);
                w.x += rv.x; w.y += rv.y; w.z += rv.z; w.w += rv.w;
            }
            *(float4*)(C + (size_t)r * Nn + c) = w;
        }
    }
}

// ---------------- RoPE on q and k (in-place in qkv buffer) ------------------
__global__ void k_rope(float* __restrict__ qkv) {
    int idx = blockIdx.x * 256 + threadIdx.x;   // 4096*16*2*32 = 4,194,304
    int i = idx & 31;  int r = idx >> 5;
    int h = r & 15;    r >>= 4;
    int qk = r & 1;    r >>= 1;                 // r = token 0..4095
    int t = r & 2047;                           // position within sequence
    float inv = powf(10000.f, -(float)i * (1.f / 32.f));
    float ang = (float)t * inv;
    float sn, cs;
    sincosf(ang, &sn, &cs);
    float* p = qkv + r * 3072 + qk * 1024 + h * 64 + 2 * i;
    float x0 = p[0], x1 = p[1];
    p[0] = x0 * cs - x1 * sn;
    p[1] = x1 * cs + x0 * sn;
}

// ---------------- fused flash attention (64x64 tiles, online softmax) -------
// grid: (32 q-tiles, 32 b*h).  smem: Qs[64][68] | KP[64][68] (K then P) | Vt[64][68]
__global__ __launch_bounds__(256) void k_attn(const float* __restrict__ qkv,
                                              float* __restrict__ out) {
    extern __shared__ float sm[];
    float* Qs = sm;
    float* KP = sm + 64 * 68;
    float* Vt = sm + 2 * 64 * 68;
    const int tid = threadIdx.x;
    const int tx = tid & 15, ty = tid >> 4;
    const int qt = blockIdx.x, bh = blockIdx.y;
    const int b = bh >> 4, h = bh & 15;
    const int base_tok = b * 2048;
    const int r0 = ty * 4, c0 = tx * 4;

    // load Q tile (pre-scaled by 1/sqrt(hd))
    #pragma unroll
    for (int f = tid; f < 1024; f += 256) {
        int row = f >> 4, dc = (f & 15) << 2;
        int tok = base_tok + qt * 64 + row;
        float4 q4 = *(const float4*)(qkv + tok * 3072 + h * 64 + dc);
        q4.x *= 0.125f; q4.y *= 0.125f; q4.z *= 0.125f; q4.w *= 0.125f;
        *(float4*)(Qs + row * 68 + dc) = q4;
    }

    float o[4][4];
    float Mr[4], Lr[4];
    #pragma unroll
    for (int i = 0; i < 4; ++i) {
        Mr[i] = -INFINITY; Lr[i] = 0.f;
        #pragma unroll
        for (int j = 0; j < 4; ++j) o[i][j] = 0.f;
    }

    for (int kt = 0; kt < 32; ++kt) {
        __syncthreads();   // previous PV reads done (and Q stores on iter 0)
        #pragma unroll
        for (int f = tid; f < 1024; f += 256) {
            int row = f >> 4, dc = (f & 15) << 2;
            int tok = base_tok + kt * 64 + row;
            float4 k4 = *(const float4*)(qkv + tok * 3072 + 1024 + h * 64 + dc);
            *(float4*)(KP + row * 68 + dc) = k4;
            float4 v4 = *(const float4*)(qkv + tok * 3072 + 2048 + h * 64 + dc);
            Vt[(dc + 0) * 68 + row] = v4.x;
            Vt[(dc + 1) * 68 + row] = v4.y;
            Vt[(dc + 2) * 68 + row] = v4.z;
            Vt[(dc + 3) * 68 + row] = v4.w;
        }
        __syncthreads();

        // S = Q K^T  (each thread: 4 rows x 4 keys)
        float s[4][4];
        #pragma unroll
        for (int i = 0; i < 4; ++i)
            #pragma unroll
            for (int j = 0; j < 4; ++j) s[i][j] = 0.f;
        #pragma unroll
        for (int d4 = 0; d4 < 16; ++d4) {
            float4 q[4], k[4];
            #pragma unroll
            for (int i = 0; i < 4; ++i) q[i] = *(const float4*)(Qs + (r0 + i) * 68 + d4 * 4);
            #pragma unroll
            for (int j = 0; j < 4; ++j) k[j] = *(const float4*)(KP + (c0 + j) * 68 + d4 * 4);
            #pragma unroll
            for (int i = 0; i < 4; ++i)
                #pragma unroll
                for (int j = 0; j < 4; ++j)
                    s[i][j] += q[i].x * k[j].x + q[i].y * k[j].y +
                               q[i].z * k[j].z + q[i].w * k[j].w;
        }

        // online softmax update (rows split across 16 tx lanes)
        #pragma unroll
        for (int i = 0; i < 4; ++i) {
            float tm = fmaxf(fmaxf(s[i][0], s[i][1]), fmaxf(s[i][2], s[i][3]));
            #pragma unroll
            for (int off = 8; off; off >>= 1) tm = fmaxf(tm, __shfl_xor_sync(0xFFFFFFFFu, tm, off));
            float mnew = fmaxf(Mr[i], tm);
            float corr = __expf(Mr[i] - mnew);
            float ls = 0.f;
            #pragma unroll
            for (int j = 0; j < 4; ++j) { s[i][j] = __expf(s[i][j] - mnew); ls += s[i][j]; }
            #pragma unroll
            for (int off = 8; off; off >>= 1) ls += __shfl_xor_sync(0xFFFFFFFFu, ls, off);
            Lr[i] = Lr[i] * corr + ls;
            Mr[i] = mnew;
            #pragma unroll
            for (int j = 0; j < 4; ++j) o[i][j] *= corr;
        }

        __syncthreads();   // everyone done reading K from KP
        #pragma unroll
        for (int i = 0; i < 4; ++i)
            *(float4*)(KP + (r0 + i) * 68 + c0) = make_float4(s[i][0], s[i][1], s[i][2], s[i][3]);
        __syncthreads();

        // O += P V   (thread: 4 rows x 4 out-dims, reduce over 64 keys)
        #pragma unroll
        for (int k4 = 0; k4 < 16; ++k4) {
            float4 p[4], v[4];
            #pragma unroll
            for (int i = 0; i < 4; ++i) p[i] = *(const float4*)(KP + (r0 + i) * 68 + k4 * 4);
            #pragma unroll
            for (int j = 0; j < 4; ++j) v[j] = *(const float4*)(Vt + (c0 + j) * 68 + k4 * 4);
            #pragma unroll
            for (int i = 0; i < 4; ++i)
                #pragma unroll
                for (int j = 0; j < 4; ++j)
                    o[i][j] += p[i].x * v[j].x + p[i].y * v[j].y +
                               p[i].z * v[j].z + p[i].w * v[j].w;
        }
    }

    #pragma unroll
    for (int i = 0; i < 4; ++i) {
        float rinv = 1.f / Lr[i];
        int tok = base_tok + qt * 64 + r0 + i;
        float4 w = make_float4(o[i][0] * rinv, o[i][1] * rinv, o[i][2] * rinv, o[i][3] * rinv);
        *(float4*)(out + tok * 1024 + h * 64 + c0) = w;
    }
}

// ---------------- SwiGLU for FFN -------------------------------------------
__global__ void k_swiglu(const float* __restrict__ u, float* __restrict__ s) {
    int idx = blockIdx.x * 256 + threadIdx.x;   // 4096*1024 float4 groups
    int m = idx >> 10, c4 = (idx & 1023) << 2;
    float4 a = *(const float4*)(u + (size_t)m * 8192 + c4);
    float4 g = *(const float4*)(u + (size_t)m * 8192 + 4096 + c4);
    float4 o;
    o.x = a.x * (g.x / (1.f + __expf(-g.x)));
    o.y = a.y * (g.y / (1.f + __expf(-g.y)));
    o.z = a.z * (g.z / (1.f + __expf(-g.z)));
    o.w = a.w * (g.w / (1.f + __expf(-g.w)));
    *(float4*)(s + (size_t)m * 4096 + c4) = o;
}

// ---------------- launcher --------------------------------------------------
extern "C" void kernel_launch(void* const* d_in, const int* in_sizes, int n_in,
                              void* d_out, int out_size) {
    const float* x     = (const float*)d_in[0];
    const float* temb  = (const float*)d_in[1];
    const float* g1    = (const float*)d_in[2];
    const float* g2    = (const float*)d_in[3];
    const float* w_qkv = (const float*)d_in[4];
    const float* b_qkv = (const float*)d_in[5];
    const float* w_ao  = (const float*)d_in[6];
    const float* b_ao  = (const float*)d_in[7];
    const float* w_fc  = (const float*)d_in[8];
    const float* b_fc  = (const float*)d_in[9];
    const float* w_fo  = (const float*)d_in[10];
    const float* b_fo  = (const float*)d_in[11];
    const float* w_t1  = (const float*)d_in[12];
    const float* b_t1  = (const float*)d_in[13];
    const float* w_t2  = (const float*)d_in[14];
    const float* b_t2  = (const float*)d_in[15];
    float* out = (float*)d_out;

    float *tpu, *tps, *tp, *h, *qkv, *att, *x1, *u, *sw;
    cudaGetSymbolAddress((void**)&tpu, g_tpu);
    cudaGetSymbolAddress((void**)&tps, g_tps);
    cudaGetSymbolAddress((void**)&tp,  g_tp);
    cudaGetSymbolAddress((void**)&h,   g_h);
    cudaGetSymbolAddress((void**)&qkv, g_qkv);
    cudaGetSymbolAddress((void**)&att, g_att);
    cudaGetSymbolAddress((void**)&x1,  g_x1);
    cudaGetSymbolAddress((void**)&u,   g_u);
    cudaGetSymbolAddress((void**)&sw,  g_sw);

    cudaFuncSetAttribute(k_attn, cudaFuncAttributeMaxDynamicSharedMemorySize, 3 * 64 * 68 * 4);

    // time-conditioning MLP -> shift/scale
    k_smallmm<<<dim3(8, 2), 256>>>(temb, w_t1, b_t1, tpu, 1024, 2048);
    k_tswiglu<<<8, 256>>>(tpu, tps);
    k_smallmm<<<dim3(16, 2), 256>>>(tps, w_t2, b_t2, tp, 1024, 4096);

    // attention branch
    k_rmsnorm<<<4096, 256>>>(x, g1, tp, 0, 1024, h);
    k_sgemm<false><<<dim3(24, 32), 256>>>(h, w_qkv, b_qkv, nullptr, qkv, 3072, 1024);
    k_rope<<<16384, 256>>>(qkv);
    k_attn<<<dim3(32, 32), 256, 3 * 64 * 68 * 4>>>(qkv, att);
    k_sgemm<true><<<dim3(8, 32), 256>>>(att, w_ao, b_ao, x, x1, 1024, 1024);

    // FFN branch
    k_rmsnorm<<<4096, 256>>>(x1, g2, tp, 2048, 3072, h);
    k_sgemm<false><<<dim3(64, 32), 256>>>(h, w_fc, b_fc, nullptr, u, 8192, 1024);
    k_swiglu<<<16384, 256>>>(u, sw);
    k_sgemm<true><<<dim3(8, 32), 256>>>(sw, w_fo, b_fo, x1, out, 1024, 4096);
}

// round 4
// speedup vs baseline: 1.5366x; 1.5366x over previous
#include <cuda_runtime.h>
#include <math.h>

// Problem constants: B=2, T=2048, D=1024, H=16, hd=64, M = B*T = 4096
#define MROWS 4096

// ---------------- scratch (device globals; no allocation allowed) ----------
__device__ float g_tpu[2 * 2048];        // time MLP hidden
__device__ float g_tps[2 * 1024];        // time MLP after swiglu
__device__ float g_tp [2 * 4096];        // shift1|scale1|shift2|scale2
__device__ float g_h  [MROWS * 1024];    // normed/modulated activations
__device__ float g_qkv[MROWS * 3072];    // qkv projections
__device__ float g_att[MROWS * 1024];    // attention output (b,t,h,d)
__device__ float g_x1 [MROWS * 1024];    // x after attention residual
__device__ float g_u  [MROWS * 8192];    // ffn pre-activation
__device__ float g_sw [MROWS * 4096];    // ffn post-swiglu

// ---------------- tiny time-MLP GEMMs (M=2) --------------------------------
__global__ void k_smallmm(const float* __restrict__ in, const float* __restrict__ w,
                          const float* __restrict__ bias, float* __restrict__ out,
                          int K, int N) {
    int n = blockIdx.x * 256 + threadIdx.x;
    int b = blockIdx.y;
    if (n >= N) return;
    float acc = bias[n];
    const float* xr = in + b * K;
    #pragma unroll 8
    for (int k = 0; k < K; ++k) acc += xr[k] * w[k * N + n];
    out[b * N + n] = acc;
}

__global__ void k_tswiglu(const float* __restrict__ u, float* __restrict__ s) {
    int i = blockIdx.x * 256 + threadIdx.x;  // 2048 total
    if (i >= 2048) return;
    int b = i >> 10, j = i & 1023;
    float a = u[b * 2048 + j];
    float g = u[b * 2048 + 1024 + j];
    s[b * 1024 + j] = a * (g / (1.f + expf(-g)));
}

// ---------------- fused RMSNorm + adaLN modulation --------------------------
__global__ __launch_bounds__(256) void k_rmsnorm(const float* __restrict__ x,
                                                 const float* __restrict__ g,
                                                 const float* __restrict__ tp,
                                                 int shift_off, int scale_off,
                                                 float* __restrict__ out) {
    int row = blockIdx.x;          // 0..4095
    int b   = row >> 11;
    const float4* xr = (const float4*)(x + row * 1024);
    float4 v = xr[threadIdx.x];    // 256 threads * 4 = 1024
    float ss = v.x * v.x + v.y * v.y + v.z * v.z + v.w * v.w;
    #pragma unroll
    for (int off = 16; off; off >>= 1) ss += __shfl_xor_sync(0xFFFFFFFFu, ss, off);
    __shared__ float wsum[8];
    __shared__ float stot;
    if ((threadIdx.x & 31) == 0) wsum[threadIdx.x >> 5] = ss;
    __syncthreads();
    if (threadIdx.x == 0) {
        float t = 0.f;
        #pragma unroll
        for (int i = 0; i < 8; ++i) t += wsum[i];
        stot = rsqrtf(t * (1.f / 1024.f) + 1.1920928955078125e-7f);
    }
    __syncthreads();
    float r = stot;
    int j = threadIdx.x * 4;
    const float* gg = g + j;
    const float* sc = tp + b * 4096 + scale_off + j;
    const float* sh = tp + b * 4096 + shift_off + j;
    float4 o;
    o.x = v.x * r * gg[0] * (1.f + sc[0]) + sh[0];
    o.y = v.y * r * gg[1] * (1.f + sc[1]) + sh[1];
    o.z = v.z * r * gg[2] * (1.f + sc[2]) + sh[2];
    o.w = v.w * r * gg[3] * (1.f + sc[3]) + sh[3];
    ((float4*)(out + row * 1024))[threadIdx.x] = o;
}

// ---------------- tf32 tensor-core GEMM ------------------------------------
// C[M,N] = A[M,K] @ B[K,N] + bias (+ residual).  Block tile 128x128, BK=16.
// 8 warps: 2 (m) x 4 (n), warp tile 64x32 via m16n8k8 tf32 mma.

__device__ __forceinline__ unsigned cvt_tf32(float f) {
    unsigned u;
    asm("cvt.rna.tf32.f32 %0, %1;" : "=r"(u) : "f"(f));
    return u;
}

__device__ __forceinline__ void mma_tf32(float* c, unsigned a0, unsigned a1,
                                         unsigned a2, unsigned a3,
                                         unsigned b0, unsigned b1) {
    asm volatile(
        "mma.sync.aligned.m16n8k8.row.col.f32.tf32.tf32.f32 "
        "{%0,%1,%2,%3}, {%4,%5,%6,%7}, {%8,%9}, {%0,%1,%2,%3};\n"
        : "+f"(c[0]), "+f"(c[1]), "+f"(c[2]), "+f"(c[3])
        : "r"(a0), "r"(a1), "r"(a2), "r"(a3), "r"(b0), "r"(b1));
}

template <bool RES>
__global__ __launch_bounds__(256) void k_tgemm(const float* __restrict__ A,
                                               const float* __restrict__ B,
                                               const float* __restrict__ bias,
                                               const float* __restrict__ res,
                                               float* __restrict__ C,
                                               int Nn, int Kn) {
    __shared__ unsigned As[128][20];   // [m][k], stride 20 -> conflict-free frag lds
    __shared__ unsigned Bs[16][136];   // [k][n], stride 136 -> conflict-free frag lds

    const int tid  = threadIdx.x;
    const int lane = tid & 31;
    const int g    = lane >> 2;        // 0..7
    const int t    = lane & 3;         // 0..3
    const int warp = tid >> 5;
    const int wm   = (warp >> 2) * 64; // 0 or 64
    const int wn   = (warp & 3) * 32;  // 0,32,64,96

    const int row0 = blockIdx.y * 128;
    const int col0 = blockIdx.x * 128;

    // global load mapping (float4-coalesced)
    const int arow = tid >> 2;         // 0..63 (and +64)
    const int ac4  = tid & 3;          // float4 index within 16-float k-chunk
    const int brow = tid >> 5;         // 0..7  (and +8)
    const int bc4  = tid & 31;         // float4 index within 128-float n-row

    const float* Ap0 = A + (size_t)(row0 + arow)      * Kn + ac4 * 4;
    const float* Ap1 = A + (size_t)(row0 + arow + 64) * Kn + ac4 * 4;
    const float* Bp0 = B + (size_t)brow       * Nn + col0 + bc4 * 4;
    const float* Bp1 = B + (size_t)(brow + 8) * Nn + col0 + bc4 * 4;

    float acc[4][4][4];
    #pragma unroll
    for (int mi = 0; mi < 4; ++mi)
        #pragma unroll
        for (int ni = 0; ni < 4; ++ni)
            #pragma unroll
            for (int r = 0; r < 4; ++r) acc[mi][ni][r] = 0.f;

    float4 pa0 = *(const float4*)Ap0;
    float4 pa1 = *(const float4*)Ap1;
    float4 pb0 = *(const float4*)Bp0;
    float4 pb1 = *(const float4*)Bp1;

    for (int k0 = 0; k0 < Kn; k0 += 16) {
        // stage current prefetched tile into smem (tf32-rounded)
        {
            uint4 u;
            u.x = cvt_tf32(pa0.x); u.y = cvt_tf32(pa0.y);
            u.z = cvt_tf32(pa0.z); u.w = cvt_tf32(pa0.w);
            *(uint4*)&As[arow][ac4 * 4] = u;
            u.x = cvt_tf32(pa1.x); u.y = cvt_tf32(pa1.y);
            u.z = cvt_tf32(pa1.z); u.w = cvt_tf32(pa1.w);
            *(uint4*)&As[arow + 64][ac4 * 4] = u;
            u.x = cvt_tf32(pb0.x); u.y = cvt_tf32(pb0.y);
            u.z = cvt_tf32(pb0.z); u.w = cvt_tf32(pb0.w);
            *(uint4*)&Bs[brow][bc4 * 4] = u;
            u.x = cvt_tf32(pb1.x); u.y = cvt_tf32(pb1.y);
            u.z = cvt_tf32(pb1.z); u.w = cvt_tf32(pb1.w);
            *(uint4*)&Bs[brow + 8][bc4 * 4] = u;
        }
        __syncthreads();

        if (k0 + 16 < Kn) {
            Ap0 += 16; Ap1 += 16;
            Bp0 += (size_t)16 * Nn; Bp1 += (size_t)16 * Nn;
            pa0 = *(const float4*)Ap0;
            pa1 = *(const float4*)Ap1;
            pb0 = *(const float4*)Bp0;
            pb1 = *(const float4*)Bp1;
        }

        #pragma unroll
        for (int sub = 0; sub < 2; ++sub) {
            const int kt = sub * 8;
            unsigned af[4][4], bf[4][2];
            #pragma unroll
            for (int mi = 0; mi < 4; ++mi) {
                int m = wm + mi * 16 + g;
                af[mi][0] = As[m]    [kt + t];
                af[mi][1] = As[m + 8][kt + t];
                af[mi][2] = As[m]    [kt + t + 4];
                af[mi][3] = As[m + 8][kt + t + 4];
            }
            #pragma unroll
            for (int ni = 0; ni < 4; ++ni) {
                int n = wn + ni * 8 + g;
                bf[ni][0] = Bs[kt + t]    [n];
                bf[ni][1] = Bs[kt + t + 4][n];
            }
            #pragma unroll
            for (int mi = 0; mi < 4; ++mi)
                #pragma unroll
                for (int ni = 0; ni < 4; ++ni)
                    mma_tf32(acc[mi][ni], af[mi][0], af[mi][1], af[mi][2], af[mi][3],
                             bf[ni][0], bf[ni][1]);
        }
        __syncthreads();
    }

    // epilogue: bias (+residual), float2 stores
    #pragma unroll
    for (int mi = 0; mi < 4; ++mi) {
        int r_top = row0 + wm + mi * 16 + g;
        int r_bot = r_top + 8;
        #pragma unroll
        for (int ni = 0; ni < 4; ++ni) {
            int c = col0 + wn + ni * 8 + 2 * t;
            float bx = bias[c], by = bias[c + 1];
            float2 w0 = make_float2(acc[mi][ni][0] + bx, acc[mi][ni][1] + by);
            float2 w1 = make_float2(acc[mi][ni][2] + bx, acc[mi][ni][3] + by);
            if (RES) {
                float2 r0 = *(const float2*)(res + (size_t)r_top * Nn + c);
                float2 r1 = *(const float2*)(res + (size_t)r_bot * Nn + c);
                w0.x += r0.x; w0.y += r0.y;
                w1.x += r1.x; w1.y += r1.y;
            }
            *(float2*)(C + (size_t)r_top * Nn + c) = w0;
            *(float2*)(C + (size_t)r_bot * Nn + c) = w1;
        }
    }
}

// ---------------- RoPE on q and k (in-place in qkv buffer) ------------------
__global__ void k_rope(float* __restrict__ qkv) {
    int idx = blockIdx.x * 256 + threadIdx.x;   // 4096*16*2*32 = 4,194,304
    int i = idx & 31;  int r = idx >> 5;
    int h = r & 15;    r >>= 4;
    int qk = r & 1;    r >>= 1;                 // r = token 0..4095
    int t = r & 2047;                           // position within sequence
    float inv = powf(10000.f, -(float)i * (1.f / 32.f));
    float ang = (float)t * inv;
    float sn, cs;
    sincosf(ang, &sn, &cs);
    float* p = qkv + r * 3072 + qk * 1024 + h * 64 + 2 * i;
    float x0 = p[0], x1 = p[1];
    p[0] = x0 * cs - x1 * sn;
    p[1] = x1 * cs + x0 * sn;
}

// ---------------- fused flash attention (64x64 tiles, online softmax) -------
__global__ __launch_bounds__(256) void k_attn(const float* __restrict__ qkv,
                                              float* __restrict__ out) {
    extern __shared__ float sm[];
    float* Qs = sm;
    float* KP = sm + 64 * 68;
    float* Vt = sm + 2 * 64 * 68;
    const int tid = threadIdx.x;
    const int tx = tid & 15, ty = tid >> 4;
    const int qt = blockIdx.x, bh = blockIdx.y;
    const int b = bh >> 4, h = bh & 15;
    const int base_tok = b * 2048;
    const int r0 = ty * 4, c0 = tx * 4;

    #pragma unroll
    for (int f = tid; f < 1024; f += 256) {
        int row = f >> 4, dc = (f & 15) << 2;
        int tok = base_tok + qt * 64 + row;
        float4 q4 = *(const float4*)(qkv + tok * 3072 + h * 64 + dc);
        q4.x *= 0.125f; q4.y *= 0.125f; q4.z *= 0.125f; q4.w *= 0.125f;
        *(float4*)(Qs + row * 68 + dc) = q4;
    }

    float o[4][4];
    float Mr[4], Lr[4];
    #pragma unroll
    for (int i = 0; i < 4; ++i) {
        Mr[i] = -INFINITY; Lr[i] = 0.f;
        #pragma unroll
        for (int j = 0; j < 4; ++j) o[i][j] = 0.f;
    }

    for (int kt = 0; kt < 32; ++kt) {
        __syncthreads();
        #pragma unroll
        for (int f = tid; f < 1024; f += 256) {
            int row = f >> 4, dc = (f & 15) << 2;
            int tok = base_tok + kt * 64 + row;
            float4 k4 = *(const float4*)(qkv + tok * 3072 + 1024 + h * 64 + dc);
            *(float4*)(KP + row * 68 + dc) = k4;
            float4 v4 = *(const float4*)(qkv + tok * 3072 + 2048 + h * 64 + dc);
            Vt[(dc + 0) * 68 + row] = v4.x;
            Vt[(dc + 1) * 68 + row] = v4.y;
            Vt[(dc + 2) * 68 + row] = v4.z;
            Vt[(dc + 3) * 68 + row] = v4.w;
        }
        __syncthreads();

        float s[4][4];
        #pragma unroll
        for (int i = 0; i < 4; ++i)
            #pragma unroll
            for (int j = 0; j < 4; ++j) s[i][j] = 0.f;
        #pragma unroll
        for (int d4 = 0; d4 < 16; ++d4) {
            float4 q[4], k[4];
            #pragma unroll
            for (int i = 0; i < 4; ++i) q[i] = *(const float4*)(Qs + (r0 + i) * 68 + d4 * 4);
            #pragma unroll
            for (int j = 0; j < 4; ++j) k[j] = *(const float4*)(KP + (c0 + j) * 68 + d4 * 4);
            #pragma unroll
            for (int i = 0; i < 4; ++i)
                #pragma unroll
                for (int j = 0; j < 4; ++j)
                    s[i][j] += q[i].x * k[j].x + q[i].y * k[j].y +
                               q[i].z * k[j].z + q[i].w * k[j].w;
        }

        #pragma unroll
        for (int i = 0; i < 4; ++i) {
            float tm = fmaxf(fmaxf(s[i][0], s[i][1]), fmaxf(s[i][2], s[i][3]));
            #pragma unroll
            for (int off = 8; off; off >>= 1) tm = fmaxf(tm, __shfl_xor_sync(0xFFFFFFFFu, tm, off));
            float mnew = fmaxf(Mr[i], tm);
            float corr = __expf(Mr[i] - mnew);
            float ls = 0.f;
            #pragma unroll
            for (int j = 0; j < 4; ++j) { s[i][j] = __expf(s[i][j] - mnew); ls += s[i][j]; }
            #pragma unroll
            for (int off = 8; off; off >>= 1) ls += __shfl_xor_sync(0xFFFFFFFFu, ls, off);
            Lr[i] = Lr[i] * corr + ls;
            Mr[i] = mnew;
            #pragma unroll
            for (int j = 0; j < 4; ++j) o[i][j] *= corr;
        }

        __syncthreads();
        #pragma unroll
        for (int i = 0; i < 4; ++i)
            *(float4*)(KP + (r0 + i) * 68 + c0) = make_float4(s[i][0], s[i][1], s[i][2], s[i][3]);
        __syncthreads();

        #pragma unroll
        for (int k4 = 0; k4 < 16; ++k4) {
            float4 p[4], v[4];
            #pragma unroll
            for (int i = 0; i < 4; ++i) p[i] = *(const float4*)(KP + (r0 + i) * 68 + k4 * 4);
            #pragma unroll
            for (int j = 0; j < 4; ++j) v[j] = *(const float4*)(Vt + (c0 + j) * 68 + k4 * 4);
            #pragma unroll
            for (int i = 0; i < 4; ++i)
                #pragma unroll
                for (int j = 0; j < 4; ++j)
                    o[i][j] += p[i].x * v[j].x + p[i].y * v[j].y +
                               p[i].z * v[j].z + p[i].w * v[j].w;
        }
    }

    #pragma unroll
    for (int i = 0; i < 4; ++i) {
        float rinv = 1.f / Lr[i];
        int tok = base_tok + qt * 64 + r0 + i;
        float4 w = make_float4(o[i][0] * rinv, o[i][1] * rinv, o[i][2] * rinv, o[i][3] * rinv);
        *(float4*)(out + tok * 1024 + h * 64 + c0) = w;
    }
}

// ---------------- SwiGLU for FFN -------------------------------------------
__global__ void k_swiglu(const float* __restrict__ u, float* __restrict__ s) {
    int idx = blockIdx.x * 256 + threadIdx.x;   // 4096*1024 float4 groups
    int m = idx >> 10, c4 = (idx & 1023) << 2;
    float4 a = *(const float4*)(u + (size_t)m * 8192 + c4);
    float4 g = *(const float4*)(u + (size_t)m * 8192 + 4096 + c4);
    float4 o;
    o.x = a.x * (g.x / (1.f + __expf(-g.x)));
    o.y = a.y * (g.y / (1.f + __expf(-g.y)));
    o.z = a.z * (g.z / (1.f + __expf(-g.z)));
    o.w = a.w * (g.w / (1.f + __expf(-g.w)));
    *(float4*)(s + (size_t)m * 4096 + c4) = o;
}

// ---------------- launcher --------------------------------------------------
extern "C" void kernel_launch(void* const* d_in, const int* in_sizes, int n_in,
                              void* d_out, int out_size) {
    const float* x     = (const float*)d_in[0];
    const float* temb  = (const float*)d_in[1];
    const float* g1    = (const float*)d_in[2];
    const float* g2    = (const float*)d_in[3];
    const float* w_qkv = (const float*)d_in[4];
    const float* b_qkv = (const float*)d_in[5];
    const float* w_ao  = (const float*)d_in[6];
    const float* b_ao  = (const float*)d_in[7];
    const float* w_fc  = (const float*)d_in[8];
    const float* b_fc  = (const float*)d_in[9];
    const float* w_fo  = (const float*)d_in[10];
    const float* b_fo  = (const float*)d_in[11];
    const float* w_t1  = (const float*)d_in[12];
    const float* b_t1  = (const float*)d_in[13];
    const float* w_t2  = (const float*)d_in[14];
    const float* b_t2  = (const float*)d_in[15];
    float* out = (float*)d_out;

    float *tpu, *tps, *tp, *h, *qkv, *att, *x1, *u, *sw;
    cudaGetSymbolAddress((void**)&tpu, g_tpu);
    cudaGetSymbolAddress((void**)&tps, g_tps);
    cudaGetSymbolAddress((void**)&tp,  g_tp);
    cudaGetSymbolAddress((void**)&h,   g_h);
    cudaGetSymbolAddress((void**)&qkv, g_qkv);
    cudaGetSymbolAddress((void**)&att, g_att);
    cudaGetSymbolAddress((void**)&x1,  g_x1);
    cudaGetSymbolAddress((void**)&u,   g_u);
    cudaGetSymbolAddress((void**)&sw,  g_sw);

    cudaFuncSetAttribute(k_attn, cudaFuncAttributeMaxDynamicSharedMemorySize, 3 * 64 * 68 * 4);

    // time-conditioning MLP -> shift/scale
    k_smallmm<<<dim3(8, 2), 256>>>(temb, w_t1, b_t1, tpu, 1024, 2048);
    k_tswiglu<<<8, 256>>>(tpu, tps);
    k_smallmm<<<dim3(16, 2), 256>>>(tps, w_t2, b_t2, tp, 1024, 4096);

    // attention branch
    k_rmsnorm<<<4096, 256>>>(x, g1, tp, 0, 1024, h);
    k_tgemm<false><<<dim3(24, 32), 256>>>(h, w_qkv, b_qkv, nullptr, qkv, 3072, 1024);
    k_rope<<<16384, 256>>>(qkv);
    k_attn<<<dim3(32, 32), 256, 3 * 64 * 68 * 4>>>(qkv, att);
    k_tgemm<true><<<dim3(8, 32), 256>>>(att, w_ao, b_ao, x, x1, 1024, 1024);

    // FFN branch
    k_rmsnorm<<<4096, 256>>>(x1, g2, tp, 2048, 3072, h);
    k_tgemm<false><<<dim3(64, 32), 256>>>(h, w_fc, b_fc, nullptr, u, 8192, 1024);
    k_swiglu<<<16384, 256>>>(u, sw);
    k_tgemm<true><<<dim3(8, 32), 256>>>(sw, w_fo, b_fo, x1, out, 1024, 4096);
}

// round 5
// speedup vs baseline: 3.3430x; 2.1756x over previous
#include <cuda_runtime.h>
#include <math.h>

// Problem constants: B=2, T=2048, D=1024, H=16, hd=64, M = B*T = 4096
#define MROWS 4096

// ---------------- scratch (device globals; no allocation allowed) ----------
__device__ float g_tpu[2 * 2048];        // time MLP hidden
__device__ float g_tps[2 * 1024];        // time MLP after swiglu
__device__ float g_tp [2 * 4096];        // shift1|scale1|shift2|scale2
__device__ float g_h  [MROWS * 1024];    // normed/modulated activations
__device__ float g_qkv[MROWS * 3072];    // qkv projections
__device__ float g_att[MROWS * 1024];    // attention output (b,t,h,d)
__device__ float g_x1 [MROWS * 1024];    // x after attention residual
__device__ float g_u  [MROWS * 8192];    // ffn pre-activation
__device__ float g_sw [MROWS * 4096];    // ffn post-swiglu

__device__ __forceinline__ unsigned cvt_tf32(float f) {
    unsigned u;
    asm("cvt.rna.tf32.f32 %0, %1;" : "=r"(u) : "f"(f));
    return u;
}

__device__ __forceinline__ void mma_tf32(float* c, unsigned a0, unsigned a1,
                                         unsigned a2, unsigned a3,
                                         unsigned b0, unsigned b1) {
    asm volatile(
        "mma.sync.aligned.m16n8k8.row.col.f32.tf32.tf32.f32 "
        "{%0,%1,%2,%3}, {%4,%5,%6,%7}, {%8,%9}, {%0,%1,%2,%3};\n"
        : "+f"(c[0]), "+f"(c[1]), "+f"(c[2]), "+f"(c[3])
        : "r"(a0), "r"(a1), "r"(a2), "r"(a3), "r"(b0), "r"(b1));
}

// ---------------- tiny time-MLP GEMMs (M=2) --------------------------------
__global__ void k_smallmm(const float* __restrict__ in, const float* __restrict__ w,
                          const float* __restrict__ bias, float* __restrict__ out,
                          int K, int N) {
    int n = blockIdx.x * 256 + threadIdx.x;
    int b = blockIdx.y;
    if (n >= N) return;
    float acc = bias[n];
    const float* xr = in + b * K;
    #pragma unroll 8
    for (int k = 0; k < K; ++k) acc += xr[k] * w[k * N + n];
    out[b * N + n] = acc;
}

__global__ void k_tswiglu(const float* __restrict__ u, float* __restrict__ s) {
    int i = blockIdx.x * 256 + threadIdx.x;  // 2048 total
    if (i >= 2048) return;
    int b = i >> 10, j = i & 1023;
    float a = u[b * 2048 + j];
    float g = u[b * 2048 + 1024 + j];
    s[b * 1024 + j] = a * (g / (1.f + expf(-g)));
}

// ---------------- fused RMSNorm + adaLN modulation --------------------------
__global__ __launch_bounds__(256) void k_rmsnorm(const float* __restrict__ x,
                                                 const float* __restrict__ g,
                                                 const float* __restrict__ tp,
                                                 int shift_off, int scale_off,
                                                 float* __restrict__ out) {
    int row = blockIdx.x;          // 0..4095
    int b   = row >> 11;
    const float4* xr = (const float4*)(x + row * 1024);
    float4 v = xr[threadIdx.x];    // 256 threads * 4 = 1024
    float ss = v.x * v.x + v.y * v.y + v.z * v.z + v.w * v.w;
    #pragma unroll
    for (int off = 16; off; off >>= 1) ss += __shfl_xor_sync(0xFFFFFFFFu, ss, off);
    __shared__ float wsum[8];
    __shared__ float stot;
    if ((threadIdx.x & 31) == 0) wsum[threadIdx.x >> 5] = ss;
    __syncthreads();
    if (threadIdx.x == 0) {
        float t = 0.f;
        #pragma unroll
        for (int i = 0; i < 8; ++i) t += wsum[i];
        stot = rsqrtf(t * (1.f / 1024.f) + 1.1920928955078125e-7f);
    }
    __syncthreads();
    float r = stot;
    int j = threadIdx.x * 4;
    const float* gg = g + j;
    const float* sc = tp + b * 4096 + scale_off + j;
    const float* sh = tp + b * 4096 + shift_off + j;
    float4 o;
    o.x = v.x * r * gg[0] * (1.f + sc[0]) + sh[0];
    o.y = v.y * r * gg[1] * (1.f + sc[1]) + sh[1];
    o.z = v.z * r * gg[2] * (1.f + sc[2]) + sh[2];
    o.w = v.w * r * gg[3] * (1.f + sc[3]) + sh[3];
    ((float4*)(out + row * 1024))[threadIdx.x] = o;
}

// ---------------- tf32 tensor-core GEMM ------------------------------------
template <bool RES>
__global__ __launch_bounds__(256) void k_tgemm(const float* __restrict__ A,
                                               const float* __restrict__ B,
                                               const float* __restrict__ bias,
                                               const float* __restrict__ res,
                                               float* __restrict__ C,
                                               int Nn, int Kn) {
    __shared__ unsigned As[128][20];
    __shared__ unsigned Bs[16][136];

    const int tid  = threadIdx.x;
    const int lane = tid & 31;
    const int g    = lane >> 2;
    const int t    = lane & 3;
    const int warp = tid >> 5;
    const int wm   = (warp >> 2) * 64;
    const int wn   = (warp & 3) * 32;

    const int row0 = blockIdx.y * 128;
    const int col0 = blockIdx.x * 128;

    const int arow = tid >> 2;
    const int ac4  = tid & 3;
    const int brow = tid >> 5;
    const int bc4  = tid & 31;

    const float* Ap0 = A + (size_t)(row0 + arow)      * Kn + ac4 * 4;
    const float* Ap1 = A + (size_t)(row0 + arow + 64) * Kn + ac4 * 4;
    const float* Bp0 = B + (size_t)brow       * Nn + col0 + bc4 * 4;
    const float* Bp1 = B + (size_t)(brow + 8) * Nn + col0 + bc4 * 4;

    float acc[4][4][4];
    #pragma unroll
    for (int mi = 0; mi < 4; ++mi)
        #pragma unroll
        for (int ni = 0; ni < 4; ++ni)
            #pragma unroll
            for (int r = 0; r < 4; ++r) acc[mi][ni][r] = 0.f;

    float4 pa0 = *(const float4*)Ap0;
    float4 pa1 = *(const float4*)Ap1;
    float4 pb0 = *(const float4*)Bp0;
    float4 pb1 = *(const float4*)Bp1;

    for (int k0 = 0; k0 < Kn; k0 += 16) {
        {
            uint4 u;
            u.x = cvt_tf32(pa0.x); u.y = cvt_tf32(pa0.y);
            u.z = cvt_tf32(pa0.z); u.w = cvt_tf32(pa0.w);
            *(uint4*)&As[arow][ac4 * 4] = u;
            u.x = cvt_tf32(pa1.x); u.y = cvt_tf32(pa1.y);
            u.z = cvt_tf32(pa1.z); u.w = cvt_tf32(pa1.w);
            *(uint4*)&As[arow + 64][ac4 * 4] = u;
            u.x = cvt_tf32(pb0.x); u.y = cvt_tf32(pb0.y);
            u.z = cvt_tf32(pb0.z); u.w = cvt_tf32(pb0.w);
            *(uint4*)&Bs[brow][bc4 * 4] = u;
            u.x = cvt_tf32(pb1.x); u.y = cvt_tf32(pb1.y);
            u.z = cvt_tf32(pb1.z); u.w = cvt_tf32(pb1.w);
            *(uint4*)&Bs[brow + 8][bc4 * 4] = u;
        }
        __syncthreads();

        if (k0 + 16 < Kn) {
            Ap0 += 16; Ap1 += 16;
            Bp0 += (size_t)16 * Nn; Bp1 += (size_t)16 * Nn;
            pa0 = *(const float4*)Ap0;
            pa1 = *(const float4*)Ap1;
            pb0 = *(const float4*)Bp0;
            pb1 = *(const float4*)Bp1;
        }

        #pragma unroll
        for (int sub = 0; sub < 2; ++sub) {
            const int kt = sub * 8;
            unsigned af[4][4], bf[4][2];
            #pragma unroll
            for (int mi = 0; mi < 4; ++mi) {
                int m = wm + mi * 16 + g;
                af[mi][0] = As[m]    [kt + t];
                af[mi][1] = As[m + 8][kt + t];
                af[mi][2] = As[m]    [kt + t + 4];
                af[mi][3] = As[m + 8][kt + t + 4];
            }
            #pragma unroll
            for (int ni = 0; ni < 4; ++ni) {
                int n = wn + ni * 8 + g;
                bf[ni][0] = Bs[kt + t]    [n];
                bf[ni][1] = Bs[kt + t + 4][n];
            }
            #pragma unroll
            for (int mi = 0; mi < 4; ++mi)
                #pragma unroll
                for (int ni = 0; ni < 4; ++ni)
                    mma_tf32(acc[mi][ni], af[mi][0], af[mi][1], af[mi][2], af[mi][3],
                             bf[ni][0], bf[ni][1]);
        }
        __syncthreads();
    }

    #pragma unroll
    for (int mi = 0; mi < 4; ++mi) {
        int r_top = row0 + wm + mi * 16 + g;
        int r_bot = r_top + 8;
        #pragma unroll
        for (int ni = 0; ni < 4; ++ni) {
            int c = col0 + wn + ni * 8 + 2 * t;
            float bx = bias[c], by = bias[c + 1];
            float2 w0 = make_float2(acc[mi][ni][0] + bx, acc[mi][ni][1] + by);
            float2 w1 = make_float2(acc[mi][ni][2] + bx, acc[mi][ni][3] + by);
            if (RES) {
                float2 r0 = *(const float2*)(res + (size_t)r_top * Nn + c);
                float2 r1 = *(const float2*)(res + (size_t)r_bot * Nn + c);
                w0.x += r0.x; w0.y += r0.y;
                w1.x += r1.x; w1.y += r1.y;
            }
            *(float2*)(C + (size_t)r_top * Nn + c) = w0;
            *(float2*)(C + (size_t)r_bot * Nn + c) = w1;
        }
    }
}

// ---------------- RoPE on q and k (in-place in qkv buffer) ------------------
__global__ void k_rope(float* __restrict__ qkv) {
    int idx = blockIdx.x * 256 + threadIdx.x;
    int i = idx & 31;  int r = idx >> 5;
    int h = r & 15;    r >>= 4;
    int qk = r & 1;    r >>= 1;
    int t = r & 2047;
    float inv = powf(10000.f, -(float)i * (1.f / 32.f));
    float ang = (float)t * inv;
    float sn, cs;
    sincosf(ang, &sn, &cs);
    float* p = qkv + r * 3072 + qk * 1024 + h * 64 + 2 * i;
    float x0 = p[0], x1 = p[1];
    p[0] = x0 * cs - x1 * sn;
    p[1] = x1 * cs + x0 * sn;
}

// ---------------- tensor-core flash attention -------------------------------
// 64x64 tiles, 4 warps x 16 q-rows, m16n8k8 tf32 mma, online softmax in regs.
// smem: QP[64][68] (Q then reused as P), Ks[64][68], Vs[64][72]
#define QP_STR 68
#define KS_STR 68
#define VS_STR 72

__global__ __launch_bounds__(128) void k_attn(const float* __restrict__ qkv,
                                              float* __restrict__ out) {
    extern __shared__ float sm[];
    float* QP = sm;                       // 64*68
    float* Ks = sm + 64 * QP_STR;         // 64*68
    float* Vs = sm + 64 * (QP_STR + KS_STR); // 64*72

    const int tid  = threadIdx.x;
    const int lane = tid & 31;
    const int g    = lane >> 2;
    const int t    = lane & 3;
    const int warp = tid >> 5;
    const int m0   = warp * 16;

    const int qt = blockIdx.x, bh = blockIdx.y;
    const int b = bh >> 4, h = bh & 15;
    const int base_tok = b * 2048;

    // ---- load Q tile into smem (scaled by 1/sqrt(hd)), tf32-rounded -------
    #pragma unroll
    for (int f = tid; f < 1024; f += 128) {
        int row = f >> 4, dc = (f & 15) << 2;
        int tok = base_tok + qt * 64 + row;
        float4 q4 = *(const float4*)(qkv + (size_t)tok * 3072 + h * 64 + dc);
        uint4 u;
        u.x = cvt_tf32(q4.x * 0.125f); u.y = cvt_tf32(q4.y * 0.125f);
        u.z = cvt_tf32(q4.z * 0.125f); u.w = cvt_tf32(q4.w * 0.125f);
        *(uint4*)(QP + row * QP_STR + dc) = u;
    }
    __syncthreads();

    // hoist Q a-frags to registers (whole head dim: 8 k-steps)
    unsigned qa[8][4];
    #pragma unroll
    for (int ks = 0; ks < 8; ++ks) {
        const unsigned* q0 = (const unsigned*)(QP + (m0 + g) * QP_STR);
        const unsigned* q1 = (const unsigned*)(QP + (m0 + g + 8) * QP_STR);
        qa[ks][0] = q0[ks * 8 + t];
        qa[ks][1] = q1[ks * 8 + t];
        qa[ks][2] = q0[ks * 8 + t + 4];
        qa[ks][3] = q1[ks * 8 + t + 4];
    }

    float o[8][4];
    #pragma unroll
    for (int j = 0; j < 8; ++j)
        #pragma unroll
        for (int r = 0; r < 4; ++r) o[j][r] = 0.f;
    float M1 = -INFINITY, M2 = -INFINITY, L1 = 0.f, L2 = 0.f;

    for (int kt = 0; kt < 32; ++kt) {
        __syncthreads();   // prior iteration's Ks/Vs reads complete
        #pragma unroll
        for (int f = tid; f < 1024; f += 128) {
            int row = f >> 4, dc = (f & 15) << 2;
            int tok = base_tok + kt * 64 + row;
            float4 k4 = *(const float4*)(qkv + (size_t)tok * 3072 + 1024 + h * 64 + dc);
            uint4 u;
            u.x = cvt_tf32(k4.x); u.y = cvt_tf32(k4.y);
            u.z = cvt_tf32(k4.z); u.w = cvt_tf32(k4.w);
            *(uint4*)(Ks + row * KS_STR + dc) = u;
            float4 v4 = *(const float4*)(qkv + (size_t)tok * 3072 + 2048 + h * 64 + dc);
            u.x = cvt_tf32(v4.x); u.y = cvt_tf32(v4.y);
            u.z = cvt_tf32(v4.z); u.w = cvt_tf32(v4.w);
            *(uint4*)(Vs + row * VS_STR + dc) = u;
        }
        __syncthreads();

        // ---- S = Q K^T : 8 n-tiles of 8 keys --------------------------------
        float s[8][4];
        #pragma unroll
        for (int j = 0; j < 8; ++j)
            #pragma unroll
            for (int r = 0; r < 4; ++r) s[j][r] = 0.f;

        #pragma unroll
        for (int ks = 0; ks < 8; ++ks) {
            unsigned kb[8][2];
            #pragma unroll
            for (int j = 0; j < 8; ++j) {
                const unsigned* kr = (const unsigned*)(Ks + (j * 8 + g) * KS_STR);
                kb[j][0] = kr[ks * 8 + t];
                kb[j][1] = kr[ks * 8 + t + 4];
            }
            #pragma unroll
            for (int j = 0; j < 8; ++j)
                mma_tf32(s[j], qa[ks][0], qa[ks][1], qa[ks][2], qa[ks][3],
                         kb[j][0], kb[j][1]);
        }

        // ---- online softmax (rows g and g+8 of this warp's 16) -------------
        float mx1 = -INFINITY, mx2 = -INFINITY;
        #pragma unroll
        for (int j = 0; j < 8; ++j) {
            mx1 = fmaxf(mx1, fmaxf(s[j][0], s[j][1]));
            mx2 = fmaxf(mx2, fmaxf(s[j][2], s[j][3]));
        }
        mx1 = fmaxf(mx1, __shfl_xor_sync(0xFFFFFFFFu, mx1, 1));
        mx1 = fmaxf(mx1, __shfl_xor_sync(0xFFFFFFFFu, mx1, 2));
        mx2 = fmaxf(mx2, __shfl_xor_sync(0xFFFFFFFFu, mx2, 1));
        mx2 = fmaxf(mx2, __shfl_xor_sync(0xFFFFFFFFu, mx2, 2));
        float mn1 = fmaxf(M1, mx1), mn2 = fmaxf(M2, mx2);
        float cr1 = __expf(M1 - mn1), cr2 = __expf(M2 - mn2);
        float l1 = 0.f, l2 = 0.f;
        #pragma unroll
        for (int j = 0; j < 8; ++j) {
            s[j][0] = __expf(s[j][0] - mn1);
            s[j][1] = __expf(s[j][1] - mn1);
            s[j][2] = __expf(s[j][2] - mn2);
            s[j][3] = __expf(s[j][3] - mn2);
            l1 += s[j][0] + s[j][1];
            l2 += s[j][2] + s[j][3];
        }
        l1 += __shfl_xor_sync(0xFFFFFFFFu, l1, 1);
        l1 += __shfl_xor_sync(0xFFFFFFFFu, l1, 2);
        l2 += __shfl_xor_sync(0xFFFFFFFFu, l2, 1);
        l2 += __shfl_xor_sync(0xFFFFFFFFu, l2, 2);
        L1 = L1 * cr1 + l1;  M1 = mn1;
        L2 = L2 * cr2 + l2;  M2 = mn2;
        #pragma unroll
        for (int j = 0; j < 8; ++j) {
            o[j][0] *= cr1; o[j][1] *= cr1;
            o[j][2] *= cr2; o[j][3] *= cr2;
        }

        // ---- P -> smem (own warp rows only), then PV mma --------------------
        #pragma unroll
        for (int j = 0; j < 8; ++j) {
            unsigned* p0 = (unsigned*)(QP + (m0 + g) * QP_STR);
            unsigned* p1 = (unsigned*)(QP + (m0 + g + 8) * QP_STR);
            p0[j * 8 + 2 * t]     = cvt_tf32(s[j][0]);
            p0[j * 8 + 2 * t + 1] = cvt_tf32(s[j][1]);
            p1[j * 8 + 2 * t]     = cvt_tf32(s[j][2]);
            p1[j * 8 + 2 * t + 1] = cvt_tf32(s[j][3]);
        }
        __syncwarp();

        #pragma unroll
        for (int ks = 0; ks < 8; ++ks) {
            const unsigned* p0 = (const unsigned*)(QP + (m0 + g) * QP_STR);
            const unsigned* p1 = (const unsigned*)(QP + (m0 + g + 8) * QP_STR);
            unsigned pa0 = p0[ks * 8 + t];
            unsigned pa1 = p1[ks * 8 + t];
            unsigned pa2 = p0[ks * 8 + t + 4];
            unsigned pa3 = p1[ks * 8 + t + 4];
            #pragma unroll
            for (int j = 0; j < 8; ++j) {
                const unsigned* vr = (const unsigned*)(Vs + (ks * 8 + t) * VS_STR);
                const unsigned* vr4 = (const unsigned*)(Vs + (ks * 8 + t + 4) * VS_STR);
                unsigned vb0 = vr[j * 8 + g];
                unsigned vb1 = vr4[j * 8 + g];
                mma_tf32(o[j], pa0, pa1, pa2, pa3, vb0, vb1);
            }
        }
    }

    // ---- normalize + write out -------------------------------------------
    float r1 = 1.f / L1, r2 = 1.f / L2;
    int row1 = base_tok + qt * 64 + m0 + g;
    int row2 = row1 + 8;
    #pragma unroll
    for (int j = 0; j < 8; ++j) {
        int c = h * 64 + j * 8 + 2 * t;
        *(float2*)(out + (size_t)row1 * 1024 + c) = make_float2(o[j][0] * r1, o[j][1] * r1);
        *(float2*)(out + (size_t)row2 * 1024 + c) = make_float2(o[j][2] * r2, o[j][3] * r2);
    }
}

// ---------------- SwiGLU for FFN -------------------------------------------
__global__ void k_swiglu(const float* __restrict__ u, float* __restrict__ s) {
    int idx = blockIdx.x * 256 + threadIdx.x;
    int m = idx >> 10, c4 = (idx & 1023) << 2;
    float4 a = *(const float4*)(u + (size_t)m * 8192 + c4);
    float4 g = *(const float4*)(u + (size_t)m * 8192 + 4096 + c4);
    float4 o;
    o.x = a.x * (g.x / (1.f + __expf(-g.x)));
    o.y = a.y * (g.y / (1.f + __expf(-g.y)));
    o.z = a.z * (g.z / (1.f + __expf(-g.z)));
    o.w = a.w * (g.w / (1.f + __expf(-g.w)));
    *(float4*)(s + (size_t)m * 4096 + c4) = o;
}

// ---------------- launcher --------------------------------------------------
extern "C" void kernel_launch(void* const* d_in, const int* in_sizes, int n_in,
                              void* d_out, int out_size) {
    const float* x     = (const float*)d_in[0];
    const float* temb  = (const float*)d_in[1];
    const float* g1    = (const float*)d_in[2];
    const float* g2    = (const float*)d_in[3];
    const float* w_qkv = (const float*)d_in[4];
    const float* b_qkv = (const float*)d_in[5];
    const float* w_ao  = (const float*)d_in[6];
    const float* b_ao  = (const float*)d_in[7];
    const float* w_fc  = (const float*)d_in[8];
    const float* b_fc  = (const float*)d_in[9];
    const float* w_fo  = (const float*)d_in[10];
    const float* b_fo  = (const float*)d_in[11];
    const float* w_t1  = (const float*)d_in[12];
    const float* b_t1  = (const float*)d_in[13];
    const float* w_t2  = (const float*)d_in[14];
    const float* b_t2  = (const float*)d_in[15];
    float* out = (float*)d_out;

    float *tpu, *tps, *tp, *h, *qkv, *att, *x1, *u, *sw;
    cudaGetSymbolAddress((void**)&tpu, g_tpu);
    cudaGetSymbolAddress((void**)&tps, g_tps);
    cudaGetSymbolAddress((void**)&tp,  g_tp);
    cudaGetSymbolAddress((void**)&h,   g_h);
    cudaGetSymbolAddress((void**)&qkv, g_qkv);
    cudaGetSymbolAddress((void**)&att, g_att);
    cudaGetSymbolAddress((void**)&x1,  g_x1);
    cudaGetSymbolAddress((void**)&u,   g_u);
    cudaGetSymbolAddress((void**)&sw,  g_sw);

    const int attn_smem = 64 * (QP_STR + KS_STR + VS_STR) * 4;
    cudaFuncSetAttribute(k_attn, cudaFuncAttributeMaxDynamicSharedMemorySize, attn_smem);

    // time-conditioning MLP -> shift/scale
    k_smallmm<<<dim3(8, 2), 256>>>(temb, w_t1, b_t1, tpu, 1024, 2048);
    k_tswiglu<<<8, 256>>>(tpu, tps);
    k_smallmm<<<dim3(16, 2), 256>>>(tps, w_t2, b_t2, tp, 1024, 4096);

    // attention branch
    k_rmsnorm<<<4096, 256>>>(x, g1, tp, 0, 1024, h);
    k_tgemm<false><<<dim3(24, 32), 256>>>(h, w_qkv, b_qkv, nullptr, qkv, 3072, 1024);
    k_rope<<<16384, 256>>>(qkv);
    k_attn<<<dim3(32, 32), 128, attn_smem>>>(qkv, att);
    k_tgemm<true><<<dim3(8, 32), 256>>>(att, w_ao, b_ao, x, x1, 1024, 1024);

    // FFN branch
    k_rmsnorm<<<4096, 256>>>(x1, g2, tp, 2048, 3072, h);
    k_tgemm<false><<<dim3(64, 32), 256>>>(h, w_fc, b_fc, nullptr, u, 8192, 1024);
    k_swiglu<<<16384, 256>>>(u, sw);
    k_tgemm<true><<<dim3(8, 32), 256>>>(sw, w_fo, b_fo, x1, out, 1024, 4096);
}

// round 6
// speedup vs baseline: 3.8424x; 1.1494x over previous
#include <cuda_runtime.h>
#include <math.h>

// Problem constants: B=2, T=2048, D=1024, H=16, hd=64, M = B*T = 4096
#define MROWS 4096

// ---------------- scratch (device globals; no allocation allowed) ----------
__device__ float g_tpu[2 * 2048];        // time MLP hidden
__device__ float g_tps[2 * 1024];        // time MLP after swiglu
__device__ float g_tp [2 * 4096];        // shift1|scale1|shift2|scale2
__device__ float g_h  [MROWS * 1024];    // normed/modulated activations
__device__ float g_qkv[MROWS * 3072];    // qkv projections (rope fused)
__device__ float g_att[MROWS * 1024];    // attention output (b,t,h,d)
__device__ float g_x1 [MROWS * 1024];    // x after attention residual
__device__ float g_u  [MROWS * 8192];    // ffn pre-activation
__device__ float g_sw [MROWS * 4096];    // ffn post-swiglu
__device__ float2 g_ropetab[2048 * 32];  // (cos, sin) per (pos, pair)

__device__ __forceinline__ unsigned cvt_tf32(float f) {
    unsigned u;
    asm("cvt.rna.tf32.f32 %0, %1;" : "=r"(u) : "f"(f));
    return u;
}

__device__ __forceinline__ void mma_tf32(float* c, unsigned a0, unsigned a1,
                                         unsigned a2, unsigned a3,
                                         unsigned b0, unsigned b1) {
    asm volatile(
        "mma.sync.aligned.m16n8k8.row.col.f32.tf32.tf32.f32 "
        "{%0,%1,%2,%3}, {%4,%5,%6,%7}, {%8,%9}, {%0,%1,%2,%3};\n"
        : "+f"(c[0]), "+f"(c[1]), "+f"(c[2]), "+f"(c[3])
        : "r"(a0), "r"(a1), "r"(a2), "r"(a3), "r"(b0), "r"(b1));
}

__device__ __forceinline__ void cp16(void* dst, const void* src) {
    unsigned ds = (unsigned)__cvta_generic_to_shared(dst);
    asm volatile("cp.async.cg.shared.global [%0], [%1], 16;\n" :: "r"(ds), "l"(src));
}
__device__ __forceinline__ void cp_commit() {
    asm volatile("cp.async.commit_group;\n");
}
template <int N>
__device__ __forceinline__ void cp_wait() {
    asm volatile("cp.async.wait_group %0;\n" :: "n"(N));
}

// ---------------- tiny time-MLP GEMMs (M=2) --------------------------------
__global__ void k_smallmm(const float* __restrict__ in, const float* __restrict__ w,
                          const float* __restrict__ bias, float* __restrict__ out,
                          int K, int N) {
    int n = blockIdx.x * 256 + threadIdx.x;
    int b = blockIdx.y;
    if (n >= N) return;
    float acc = bias[n];
    const float* xr = in + b * K;
    #pragma unroll 8
    for (int k = 0; k < K; ++k) acc += xr[k] * w[k * N + n];
    out[b * N + n] = acc;
}

__global__ void k_tswiglu(const float* __restrict__ u, float* __restrict__ s) {
    int i = blockIdx.x * 256 + threadIdx.x;  // 2048 total
    if (i >= 2048) return;
    int b = i >> 10, j = i & 1023;
    float a = u[b * 2048 + j];
    float g = u[b * 2048 + 1024 + j];
    s[b * 1024 + j] = a * (g / (1.f + expf(-g)));
}

// ---------------- rope cos/sin table ---------------------------------------
__global__ void k_ropetab(float2* __restrict__ tab) {
    int idx = blockIdx.x * 256 + threadIdx.x;   // 65536
    int t = idx >> 5, i = idx & 31;
    float inv = powf(10000.f, -(float)i * (1.f / 32.f));
    float sn, cs;
    sincosf((float)t * inv, &sn, &cs);
    tab[idx] = make_float2(cs, sn);
}

// ---------------- fused RMSNorm + adaLN modulation --------------------------
__global__ __launch_bounds__(256) void k_rmsnorm(const float* __restrict__ x,
                                                 const float* __restrict__ g,
                                                 const float* __restrict__ tp,
                                                 int shift_off, int scale_off,
                                                 float* __restrict__ out) {
    int row = blockIdx.x;          // 0..4095
    int b   = row >> 11;
    const float4* xr = (const float4*)(x + row * 1024);
    float4 v = xr[threadIdx.x];
    float ss = v.x * v.x + v.y * v.y + v.z * v.z + v.w * v.w;
    #pragma unroll
    for (int off = 16; off; off >>= 1) ss += __shfl_xor_sync(0xFFFFFFFFu, ss, off);
    __shared__ float wsum[8];
    __shared__ float stot;
    if ((threadIdx.x & 31) == 0) wsum[threadIdx.x >> 5] = ss;
    __syncthreads();
    if (threadIdx.x == 0) {
        float t = 0.f;
        #pragma unroll
        for (int i = 0; i < 8; ++i) t += wsum[i];
        stot = rsqrtf(t * (1.f / 1024.f) + 1.1920928955078125e-7f);
    }
    __syncthreads();
    float r = stot;
    int j = threadIdx.x * 4;
    const float* gg = g + j;
    const float* sc = tp + b * 4096 + scale_off + j;
    const float* sh = tp + b * 4096 + shift_off + j;
    float4 o;
    o.x = v.x * r * gg[0] * (1.f + sc[0]) + sh[0];
    o.y = v.y * r * gg[1] * (1.f + sc[1]) + sh[1];
    o.z = v.z * r * gg[2] * (1.f + sc[2]) + sh[2];
    o.w = v.w * r * gg[3] * (1.f + sc[3]) + sh[3];
    ((float4*)(out + row * 1024))[threadIdx.x] = o;
}

// ---------------- tf32 tensor-core GEMM, cp.async double-buffered ----------
// C[M,N] = A[M,K] @ B[K,N] + bias (+residual) (+rope on cols<2048).
// Block 128x128, BK=16, 8 warps 2x4, warp tile 64x32, m16n8k8.
// fp32 bits fed directly to tf32 mma (hardware truncation).
template <bool RES, bool ROPE>
__global__ __launch_bounds__(256) void k_tgemm(const float* __restrict__ A,
                                               const float* __restrict__ B,
                                               const float* __restrict__ bias,
                                               const float* __restrict__ res,
                                               const float2* __restrict__ rtab,
                                               float* __restrict__ C,
                                               int Nn, int Kn) {
    __shared__ unsigned As[2][128][20];
    __shared__ unsigned Bs[2][16][136];

    const int tid  = threadIdx.x;
    const int lane = tid & 31;
    const int g    = lane >> 2;
    const int t    = lane & 3;
    const int warp = tid >> 5;
    const int wm   = (warp >> 2) * 64;
    const int wn   = (warp & 3) * 32;

    const int row0 = blockIdx.y * 128;
    const int col0 = blockIdx.x * 128;

    const int arow = tid >> 2;         // 0..63 (+64)
    const int ac4  = tid & 3;
    const int brow = tid >> 5;         // 0..7 (+8)
    const int bc4  = tid & 31;

    const float* Ap0 = A + (size_t)(row0 + arow)      * Kn + ac4 * 4;
    const float* Ap1 = A + (size_t)(row0 + arow + 64) * Kn + ac4 * 4;
    const float* Bp0 = B + (size_t)brow       * Nn + col0 + bc4 * 4;
    const float* Bp1 = B + (size_t)(brow + 8) * Nn + col0 + bc4 * 4;

    float acc[4][4][4];
    #pragma unroll
    for (int mi = 0; mi < 4; ++mi)
        #pragma unroll
        for (int ni = 0; ni < 4; ++ni)
            #pragma unroll
            for (int r = 0; r < 4; ++r) acc[mi][ni][r] = 0.f;

    // prologue: stage 0
    cp16(&As[0][arow][ac4 * 4],      Ap0);
    cp16(&As[0][arow + 64][ac4 * 4], Ap1);
    cp16(&Bs[0][brow][bc4 * 4],      Bp0);
    cp16(&Bs[0][brow + 8][bc4 * 4],  Bp1);
    cp_commit();

    int buf = 0;
    for (int k0 = 0; k0 < Kn; k0 += 16, buf ^= 1) {
        const bool more = (k0 + 16 < Kn);
        if (more) {
            Ap0 += 16; Ap1 += 16;
            Bp0 += (size_t)16 * Nn; Bp1 += (size_t)16 * Nn;
            int nb = buf ^ 1;
            cp16(&As[nb][arow][ac4 * 4],      Ap0);
            cp16(&As[nb][arow + 64][ac4 * 4], Ap1);
            cp16(&Bs[nb][brow][bc4 * 4],      Bp0);
            cp16(&Bs[nb][brow + 8][bc4 * 4],  Bp1);
            cp_commit();
            cp_wait<1>();
        } else {
            cp_wait<0>();
        }
        __syncthreads();

        #pragma unroll
        for (int sub = 0; sub < 2; ++sub) {
            const int kt = sub * 8;
            unsigned af[4][4], bf[4][2];
            #pragma unroll
            for (int mi = 0; mi < 4; ++mi) {
                int m = wm + mi * 16 + g;
                af[mi][0] = As[buf][m]    [kt + t];
                af[mi][1] = As[buf][m + 8][kt + t];
                af[mi][2] = As[buf][m]    [kt + t + 4];
                af[mi][3] = As[buf][m + 8][kt + t + 4];
            }
            #pragma unroll
            for (int ni = 0; ni < 4; ++ni) {
                int n = wn + ni * 8 + g;
                bf[ni][0] = Bs[buf][kt + t]    [n];
                bf[ni][1] = Bs[buf][kt + t + 4][n];
            }
            #pragma unroll
            for (int mi = 0; mi < 4; ++mi)
                #pragma unroll
                for (int ni = 0; ni < 4; ++ni)
                    mma_tf32(acc[mi][ni], af[mi][0], af[mi][1], af[mi][2], af[mi][3],
                             bf[ni][0], bf[ni][1]);
        }
        __syncthreads();
    }

    // epilogue: bias (+residual) (+rope)
    #pragma unroll
    for (int mi = 0; mi < 4; ++mi) {
        int r_top = row0 + wm + mi * 16 + g;
        int r_bot = r_top + 8;
        #pragma unroll
        for (int ni = 0; ni < 4; ++ni) {
            int c = col0 + wn + ni * 8 + 2 * t;   // even column
            float bx = bias[c], by = bias[c + 1];
            float2 w0 = make_float2(acc[mi][ni][0] + bx, acc[mi][ni][1] + by);
            float2 w1 = make_float2(acc[mi][ni][2] + bx, acc[mi][ni][3] + by);
            if (RES) {
                float2 r0 = *(const float2*)(res + (size_t)r_top * Nn + c);
                float2 r1 = *(const float2*)(res + (size_t)r_bot * Nn + c);
                w0.x += r0.x; w0.y += r0.y;
                w1.x += r1.x; w1.y += r1.y;
            }
            if (ROPE && c < 2048) {            // q,k columns get rope
                int i = (c & 63) >> 1;
                float2 cs0 = rtab[(r_top & 2047) * 32 + i];
                float2 cs1 = rtab[(r_bot & 2047) * 32 + i];
                float a0 = w0.x, a1 = w0.y;
                w0.x = a0 * cs0.x - a1 * cs0.y;
                w0.y = a1 * cs0.x + a0 * cs0.y;
                a0 = w1.x; a1 = w1.y;
                w1.x = a0 * cs1.x - a1 * cs1.y;
                w1.y = a1 * cs1.x + a0 * cs1.y;
            }
            *(float2*)(C + (size_t)r_top * Nn + c) = w0;
            *(float2*)(C + (size_t)r_bot * Nn + c) = w1;
        }
    }
}

// ---------------- tensor-core flash attention -------------------------------
#define QP_STR 68
#define KS_STR 68
#define VS_STR 72

__global__ __launch_bounds__(128) void k_attn(const float* __restrict__ qkv,
                                              float* __restrict__ out) {
    extern __shared__ float sm[];
    float* QP = sm;
    float* Ks = sm + 64 * QP_STR;
    float* Vs = sm + 64 * (QP_STR + KS_STR);

    const int tid  = threadIdx.x;
    const int lane = tid & 31;
    const int g    = lane >> 2;
    const int t    = lane & 3;
    const int warp = tid >> 5;
    const int m0   = warp * 16;

    const int qt = blockIdx.x, bh = blockIdx.y;
    const int b = bh >> 4, h = bh & 15;
    const int base_tok = b * 2048;

    #pragma unroll
    for (int f = tid; f < 1024; f += 128) {
        int row = f >> 4, dc = (f & 15) << 2;
        int tok = base_tok + qt * 64 + row;
        float4 q4 = *(const float4*)(qkv + (size_t)tok * 3072 + h * 64 + dc);
        uint4 u;
        u.x = cvt_tf32(q4.x * 0.125f); u.y = cvt_tf32(q4.y * 0.125f);
        u.z = cvt_tf32(q4.z * 0.125f); u.w = cvt_tf32(q4.w * 0.125f);
        *(uint4*)(QP + row * QP_STR + dc) = u;
    }
    __syncthreads();

    unsigned qa[8][4];
    #pragma unroll
    for (int ks = 0; ks < 8; ++ks) {
        const unsigned* q0 = (const unsigned*)(QP + (m0 + g) * QP_STR);
        const unsigned* q1 = (const unsigned*)(QP + (m0 + g + 8) * QP_STR);
        qa[ks][0] = q0[ks * 8 + t];
        qa[ks][1] = q1[ks * 8 + t];
        qa[ks][2] = q0[ks * 8 + t + 4];
        qa[ks][3] = q1[ks * 8 + t + 4];
    }

    float o[8][4];
    #pragma unroll
    for (int j = 0; j < 8; ++j)
        #pragma unroll
        for (int r = 0; r < 4; ++r) o[j][r] = 0.f;
    float M1 = -INFINITY, M2 = -INFINITY, L1 = 0.f, L2 = 0.f;

    for (int kt = 0; kt < 32; ++kt) {
        __syncthreads();
        #pragma unroll
        for (int f = tid; f < 1024; f += 128) {
            int row = f >> 4, dc = (f & 15) << 2;
            int tok = base_tok + kt * 64 + row;
            float4 k4 = *(const float4*)(qkv + (size_t)tok * 3072 + 1024 + h * 64 + dc);
            uint4 u;
            u.x = cvt_tf32(k4.x); u.y = cvt_tf32(k4.y);
            u.z = cvt_tf32(k4.z); u.w = cvt_tf32(k4.w);
            *(uint4*)(Ks + row * KS_STR + dc) = u;
            float4 v4 = *(const float4*)(qkv + (size_t)tok * 3072 + 2048 + h * 64 + dc);
            u.x = cvt_tf32(v4.x); u.y = cvt_tf32(v4.y);
            u.z = cvt_tf32(v4.z); u.w = cvt_tf32(v4.w);
            *(uint4*)(Vs + row * VS_STR + dc) = u;
        }
        __syncthreads();

        float s[8][4];
        #pragma unroll
        for (int j = 0; j < 8; ++j)
            #pragma unroll
            for (int r = 0; r < 4; ++r) s[j][r] = 0.f;

        #pragma unroll
        for (int ks = 0; ks < 8; ++ks) {
            unsigned kb[8][2];
            #pragma unroll
            for (int j = 0; j < 8; ++j) {
                const unsigned* kr = (const unsigned*)(Ks + (j * 8 + g) * KS_STR);
                kb[j][0] = kr[ks * 8 + t];
                kb[j][1] = kr[ks * 8 + t + 4];
            }
            #pragma unroll
            for (int j = 0; j < 8; ++j)
                mma_tf32(s[j], qa[ks][0], qa[ks][1], qa[ks][2], qa[ks][3],
                         kb[j][0], kb[j][1]);
        }

        float mx1 = -INFINITY, mx2 = -INFINITY;
        #pragma unroll
        for (int j = 0; j < 8; ++j) {
            mx1 = fmaxf(mx1, fmaxf(s[j][0], s[j][1]));
            mx2 = fmaxf(mx2, fmaxf(s[j][2], s[j][3]));
        }
        mx1 = fmaxf(mx1, __shfl_xor_sync(0xFFFFFFFFu, mx1, 1));
        mx1 = fmaxf(mx1, __shfl_xor_sync(0xFFFFFFFFu, mx1, 2));
        mx2 = fmaxf(mx2, __shfl_xor_sync(0xFFFFFFFFu, mx2, 1));
        mx2 = fmaxf(mx2, __shfl_xor_sync(0xFFFFFFFFu, mx2, 2));
        float mn1 = fmaxf(M1, mx1), mn2 = fmaxf(M2, mx2);
        float cr1 = __expf(M1 - mn1), cr2 = __expf(M2 - mn2);
        float l1 = 0.f, l2 = 0.f;
        #pragma unroll
        for (int j = 0; j < 8; ++j) {
            s[j][0] = __expf(s[j][0] - mn1);
            s[j][1] = __expf(s[j][1] - mn1);
            s[j][2] = __expf(s[j][2] - mn2);
            s[j][3] = __expf(s[j][3] - mn2);
            l1 += s[j][0] + s[j][1];
            l2 += s[j][2] + s[j][3];
        }
        l1 += __shfl_xor_sync(0xFFFFFFFFu, l1, 1);
        l1 += __shfl_xor_sync(0xFFFFFFFFu, l1, 2);
        l2 += __shfl_xor_sync(0xFFFFFFFFu, l2, 1);
        l2 += __shfl_xor_sync(0xFFFFFFFFu, l2, 2);
        L1 = L1 * cr1 + l1;  M1 = mn1;
        L2 = L2 * cr2 + l2;  M2 = mn2;
        #pragma unroll
        for (int j = 0; j < 8; ++j) {
            o[j][0] *= cr1; o[j][1] *= cr1;
            o[j][2] *= cr2; o[j][3] *= cr2;
        }

        #pragma unroll
        for (int j = 0; j < 8; ++j) {
            unsigned* p0 = (unsigned*)(QP + (m0 + g) * QP_STR);
            unsigned* p1 = (unsigned*)(QP + (m0 + g + 8) * QP_STR);
            p0[j * 8 + 2 * t]     = cvt_tf32(s[j][0]);
            p0[j * 8 + 2 * t + 1] = cvt_tf32(s[j][1]);
            p1[j * 8 + 2 * t]     = cvt_tf32(s[j][2]);
            p1[j * 8 + 2 * t + 1] = cvt_tf32(s[j][3]);
        }
        __syncwarp();

        #pragma unroll
        for (int ks = 0; ks < 8; ++ks) {
            const unsigned* p0 = (const unsigned*)(QP + (m0 + g) * QP_STR);
            const unsigned* p1 = (const unsigned*)(QP + (m0 + g + 8) * QP_STR);
            unsigned pa0 = p0[ks * 8 + t];
            unsigned pa1 = p1[ks * 8 + t];
            unsigned pa2 = p0[ks * 8 + t + 4];
            unsigned pa3 = p1[ks * 8 + t + 4];
            #pragma unroll
            for (int j = 0; j < 8; ++j) {
                const unsigned* vr  = (const unsigned*)(Vs + (ks * 8 + t) * VS_STR);
                const unsigned* vr4 = (const unsigned*)(Vs + (ks * 8 + t + 4) * VS_STR);
                unsigned vb0 = vr[j * 8 + g];
                unsigned vb1 = vr4[j * 8 + g];
                mma_tf32(o[j], pa0, pa1, pa2, pa3, vb0, vb1);
            }
        }
    }

    float r1 = 1.f / L1, r2 = 1.f / L2;
    int row1 = base_tok + qt * 64 + m0 + g;
    int row2 = row1 + 8;
    #pragma unroll
    for (int j = 0; j < 8; ++j) {
        int c = h * 64 + j * 8 + 2 * t;
        *(float2*)(out + (size_t)row1 * 1024 + c) = make_float2(o[j][0] * r1, o[j][1] * r1);
        *(float2*)(out + (size_t)row2 * 1024 + c) = make_float2(o[j][2] * r2, o[j][3] * r2);
    }
}

// ---------------- SwiGLU for FFN -------------------------------------------
__global__ void k_swiglu(const float* __restrict__ u, float* __restrict__ s) {
    int idx = blockIdx.x * 256 + threadIdx.x;
    int m = idx >> 10, c4 = (idx & 1023) << 2;
    float4 a = *(const float4*)(u + (size_t)m * 8192 + c4);
    float4 g = *(const float4*)(u + (size_t)m * 8192 + 4096 + c4);
    float4 o;
    o.x = a.x * (g.x / (1.f + __expf(-g.x)));
    o.y = a.y * (g.y / (1.f + __expf(-g.y)));
    o.z = a.z * (g.z / (1.f + __expf(-g.z)));
    o.w = a.w * (g.w / (1.f + __expf(-g.w)));
    *(float4*)(s + (size_t)m * 4096 + c4) = o;
}

// ---------------- launcher --------------------------------------------------
extern "C" void kernel_launch(void* const* d_in, const int* in_sizes, int n_in,
                              void* d_out, int out_size) {
    const float* x     = (const float*)d_in[0];
    const float* temb  = (const float*)d_in[1];
    const float* g1    = (const float*)d_in[2];
    const float* g2    = (const float*)d_in[3];
    const float* w_qkv = (const float*)d_in[4];
    const float* b_qkv = (const float*)d_in[5];
    const float* w_ao  = (const float*)d_in[6];
    const float* b_ao  = (const float*)d_in[7];
    const float* w_fc  = (const float*)d_in[8];
    const float* b_fc  = (const float*)d_in[9];
    const float* w_fo  = (const float*)d_in[10];
    const float* b_fo  = (const float*)d_in[11];
    const float* w_t1  = (const float*)d_in[12];
    const float* b_t1  = (const float*)d_in[13];
    const float* w_t2  = (const float*)d_in[14];
    const float* b_t2  = (const float*)d_in[15];
    float* out = (float*)d_out;

    float *tpu, *tps, *tp, *h, *qkv, *att, *x1, *u, *sw;
    float2* rtab;
    cudaGetSymbolAddress((void**)&tpu, g_tpu);
    cudaGetSymbolAddress((void**)&tps, g_tps);
    cudaGetSymbolAddress((void**)&tp,  g_tp);
    cudaGetSymbolAddress((void**)&h,   g_h);
    cudaGetSymbolAddress((void**)&qkv, g_qkv);
    cudaGetSymbolAddress((void**)&att, g_att);
    cudaGetSymbolAddress((void**)&x1,  g_x1);
    cudaGetSymbolAddress((void**)&u,   g_u);
    cudaGetSymbolAddress((void**)&sw,  g_sw);
    cudaGetSymbolAddress((void**)&rtab, g_ropetab);

    const int attn_smem = 64 * (QP_STR + KS_STR + VS_STR) * 4;
    cudaFuncSetAttribute(k_attn, cudaFuncAttributeMaxDynamicSharedMemorySize, attn_smem);

    // rope table + time-conditioning MLP
    k_ropetab<<<256, 256>>>(rtab);
    k_smallmm<<<dim3(8, 2), 256>>>(temb, w_t1, b_t1, tpu, 1024, 2048);
    k_tswiglu<<<8, 256>>>(tpu, tps);
    k_smallmm<<<dim3(16, 2), 256>>>(tps, w_t2, b_t2, tp, 1024, 4096);

    // attention branch
    k_rmsnorm<<<4096, 256>>>(x, g1, tp, 0, 1024, h);
    k_tgemm<false, true><<<dim3(24, 32), 256>>>(h, w_qkv, b_qkv, nullptr, rtab, qkv, 3072, 1024);
    k_attn<<<dim3(32, 32), 128, attn_smem>>>(qkv, att);
    k_tgemm<true, false><<<dim3(8, 32), 256>>>(att, w_ao, b_ao, x, rtab, x1, 1024, 1024);

    // FFN branch
    k_rmsnorm<<<4096, 256>>>(x1, g2, tp, 2048, 3072, h);
    k_tgemm<false, false><<<dim3(64, 32), 256>>>(h, w_fc, b_fc, nullptr, rtab, u, 8192, 1024);
    k_swiglu<<<16384, 256>>>(u, sw);
    k_tgemm<true, false><<<dim3(8, 32), 256>>>(sw, w_fo, b_fo, x1, rtab, out, 1024, 4096);
}

// round 7
// speedup vs baseline: 4.1922x; 1.0910x over previous
#include <cuda_runtime.h>
#include <math.h>

// Problem constants: B=2, T=2048, D=1024, H=16, hd=64, M = B*T = 4096
#define MROWS 4096

// ---------------- scratch (device globals; no allocation allowed) ----------
__device__ float g_tpu [2 * 2048];       // time MLP hidden
__device__ float g_tps [2 * 1024];       // time MLP after swiglu
__device__ float g_tp  [2 * 4096];       // shift1|scale1|shift2|scale2
__device__ float g_part[8 * 2 * 4096];   // split-K partials for time MLP
__device__ float g_h   [MROWS * 1024];   // normed/modulated activations
__device__ float g_qkv [MROWS * 3072];   // qkv projections (rope fused)
__device__ float g_att [MROWS * 1024];   // attention output (b,t,h,d)
__device__ float g_x1  [MROWS * 1024];   // x after attention residual
__device__ float g_u   [MROWS * 8192];   // ffn pre-activation
__device__ float g_sw  [MROWS * 4096];   // ffn post-swiglu
__device__ float2 g_ropetab[2048 * 32];  // (cos, sin) per (pos, pair)

__device__ __forceinline__ unsigned cvt_tf32(float f) {
    unsigned u;
    asm("cvt.rna.tf32.f32 %0, %1;" : "=r"(u) : "f"(f));
    return u;
}

__device__ __forceinline__ void mma_tf32(float* c, unsigned a0, unsigned a1,
                                         unsigned a2, unsigned a3,
                                         unsigned b0, unsigned b1) {
    asm volatile(
        "mma.sync.aligned.m16n8k8.row.col.f32.tf32.tf32.f32 "
        "{%0,%1,%2,%3}, {%4,%5,%6,%7}, {%8,%9}, {%0,%1,%2,%3};\n"
        : "+f"(c[0]), "+f"(c[1]), "+f"(c[2]), "+f"(c[3])
        : "r"(a0), "r"(a1), "r"(a2), "r"(a3), "r"(b0), "r"(b1));
}

__device__ __forceinline__ void cp16(void* dst, const void* src) {
    unsigned ds = (unsigned)__cvta_generic_to_shared(dst);
    asm volatile("cp.async.cg.shared.global [%0], [%1], 16;\n" :: "r"(ds), "l"(src));
}
__device__ __forceinline__ void cp_commit() {
    asm volatile("cp.async.commit_group;\n");
}
template <int N>
__device__ __forceinline__ void cp_wait() {
    asm volatile("cp.async.wait_group %0;\n" :: "n"(N));
}

// ---------------- time-MLP: split-K partial GEMM + reduce -------------------
// partials: part[(s*2+b)*4096 + n] over k-slice s (K=1024, 8 slices of 128)
__global__ __launch_bounds__(128) void k_tpart(const float* __restrict__ in,
                                               const float* __restrict__ w,
                                               float* __restrict__ part,
                                               int K, int N) {
    int n = blockIdx.x * 128 + threadIdx.x;
    int b = blockIdx.y, s = blockIdx.z;
    const float* xr = in + b * K + s * 128;
    const float* wp = w + (size_t)(s * 128) * N + n;
    float acc = 0.f;
    #pragma unroll 8
    for (int k = 0; k < 128; ++k) acc += xr[k] * wp[(size_t)k * N];
    part[(s * 2 + b) * 4096 + n] = acc;
}

__global__ void k_treduce(const float* __restrict__ part,
                          const float* __restrict__ bias,
                          float* __restrict__ out, int N) {
    int n = blockIdx.x * 256 + threadIdx.x;
    int b = blockIdx.y;
    if (n >= N) return;
    float acc = bias[n];
    #pragma unroll
    for (int s = 0; s < 8; ++s) acc += part[(s * 2 + b) * 4096 + n];
    out[b * N + n] = acc;
}

__global__ void k_tswiglu(const float* __restrict__ u, float* __restrict__ s) {
    int i = blockIdx.x * 256 + threadIdx.x;  // 2048 total
    if (i >= 2048) return;
    int b = i >> 10, j = i & 1023;
    float a = u[b * 2048 + j];
    float g = u[b * 2048 + 1024 + j];
    s[b * 1024 + j] = a * (g / (1.f + expf(-g)));
}

// ---------------- rope cos/sin table ---------------------------------------
__global__ void k_ropetab(float2* __restrict__ tab) {
    int idx = blockIdx.x * 256 + threadIdx.x;   // 65536
    int t = idx >> 5, i = idx & 31;
    float inv = powf(10000.f, -(float)i * (1.f / 32.f));
    float sn, cs;
    sincosf((float)t * inv, &sn, &cs);
    tab[idx] = make_float2(cs, sn);
}

// ---------------- fused RMSNorm + adaLN modulation --------------------------
__global__ __launch_bounds__(256) void k_rmsnorm(const float* __restrict__ x,
                                                 const float* __restrict__ g,
                                                 const float* __restrict__ tp,
                                                 int shift_off, int scale_off,
                                                 float* __restrict__ out) {
    int row = blockIdx.x;          // 0..4095
    int b   = row >> 11;
    const float4* xr = (const float4*)(x + row * 1024);
    float4 v = xr[threadIdx.x];
    float ss = v.x * v.x + v.y * v.y + v.z * v.z + v.w * v.w;
    #pragma unroll
    for (int off = 16; off; off >>= 1) ss += __shfl_xor_sync(0xFFFFFFFFu, ss, off);
    __shared__ float wsum[8];
    __shared__ float stot;
    if ((threadIdx.x & 31) == 0) wsum[threadIdx.x >> 5] = ss;
    __syncthreads();
    if (threadIdx.x == 0) {
        float t = 0.f;
        #pragma unroll
        for (int i = 0; i < 8; ++i) t += wsum[i];
        stot = rsqrtf(t * (1.f / 1024.f) + 1.1920928955078125e-7f);
    }
    __syncthreads();
    float r = stot;
    int j = threadIdx.x * 4;
    const float* gg = g + j;
    const float* sc = tp + b * 4096 + scale_off + j;
    const float* sh = tp + b * 4096 + shift_off + j;
    float4 o;
    o.x = v.x * r * gg[0] * (1.f + sc[0]) + sh[0];
    o.y = v.y * r * gg[1] * (1.f + sc[1]) + sh[1];
    o.z = v.z * r * gg[2] * (1.f + sc[2]) + sh[2];
    o.w = v.w * r * gg[3] * (1.f + sc[3]) + sh[3];
    ((float4*)(out + row * 1024))[threadIdx.x] = o;
}

// ---------------- tf32 tensor-core GEMM, 3-stage cp.async pipeline ----------
// Block 128x128, BK=16, 8 warps 2x4, warp tile 64x32, m16n8k8.
// Fragments rounded to nearest tf32 via +0x1000 half-ulp carry after LDS.
#define AS(s, m, k) Asm[((s) * 128 + (m)) * 20 + (k)]
#define BS(s, r, n) Bsm[((s) * 16 + (r)) * 136 + (n)]
#define GEMM_SMEM ((3 * 128 * 20 + 3 * 16 * 136) * 4)

template <bool RES, bool ROPE>
__global__ __launch_bounds__(256) void k_tgemm(const float* __restrict__ A,
                                               const float* __restrict__ B,
                                               const float* __restrict__ bias,
                                               const float* __restrict__ res,
                                               const float2* __restrict__ rtab,
                                               float* __restrict__ C,
                                               int Nn, int Kn) {
    extern __shared__ unsigned smemraw[];
    unsigned* Asm = smemraw;                    // [3][128][20]
    unsigned* Bsm = smemraw + 3 * 128 * 20;     // [3][16][136]

    const int tid  = threadIdx.x;
    const int lane = tid & 31;
    const int g    = lane >> 2;
    const int t    = lane & 3;
    const int warp = tid >> 5;
    const int wm   = (warp >> 2) * 64;
    const int wn   = (warp & 3) * 32;

    const int row0 = blockIdx.y * 128;
    const int col0 = blockIdx.x * 128;

    const int arow = tid >> 2;         // 0..63 (+64)
    const int ac4  = tid & 3;
    const int brow = tid >> 5;         // 0..7 (+8)
    const int bc4  = tid & 31;

    const float* Ap0 = A + (size_t)(row0 + arow)      * Kn + ac4 * 4;
    const float* Ap1 = A + (size_t)(row0 + arow + 64) * Kn + ac4 * 4;
    const float* Bp0 = B + (size_t)brow       * Nn + col0 + bc4 * 4;
    const float* Bp1 = B + (size_t)(brow + 8) * Nn + col0 + bc4 * 4;

    float acc[4][4][4];
    #pragma unroll
    for (int mi = 0; mi < 4; ++mi)
        #pragma unroll
        for (int ni = 0; ni < 4; ++ni)
            #pragma unroll
            for (int r = 0; r < 4; ++r) acc[mi][ni][r] = 0.f;

    const int tiles = Kn >> 4;

    // prologue: stages 0 and 1
    #pragma unroll
    for (int s = 0; s < 2; ++s) {
        cp16(&AS(s, arow, ac4 * 4),      Ap0);
        cp16(&AS(s, arow + 64, ac4 * 4), Ap1);
        cp16(&BS(s, brow, bc4 * 4),      Bp0);
        cp16(&BS(s, brow + 8, bc4 * 4),  Bp1);
        cp_commit();
        Ap0 += 16; Ap1 += 16;
        Bp0 += (size_t)16 * Nn; Bp1 += (size_t)16 * Nn;
    }

    for (int i = 0; i < tiles; ++i) {
        const int buf = i % 3;
        cp_wait<1>();
        __syncthreads();
        if (i + 2 < tiles) {
            const int nb = (i + 2) % 3;
            cp16(&AS(nb, arow, ac4 * 4),      Ap0);
            cp16(&AS(nb, arow + 64, ac4 * 4), Ap1);
            cp16(&BS(nb, brow, bc4 * 4),      Bp0);
            cp16(&BS(nb, brow + 8, bc4 * 4),  Bp1);
            Ap0 += 16; Ap1 += 16;
            Bp0 += (size_t)16 * Nn; Bp1 += (size_t)16 * Nn;
        }
        cp_commit();   // always commit (keeps wait<1> semantics on the tail)

        #pragma unroll
        for (int sub = 0; sub < 2; ++sub) {
            const int kt = sub * 8;
            unsigned af[4][4], bf[4][2];
            #pragma unroll
            for (int mi = 0; mi < 4; ++mi) {
                int m = wm + mi * 16 + g;
                af[mi][0] = AS(buf, m,     kt + t)     + 0x1000u;
                af[mi][1] = AS(buf, m + 8, kt + t)     + 0x1000u;
                af[mi][2] = AS(buf, m,     kt + t + 4) + 0x1000u;
                af[mi][3] = AS(buf, m + 8, kt + t + 4) + 0x1000u;
            }
            #pragma unroll
            for (int ni = 0; ni < 4; ++ni) {
                int n = wn + ni * 8 + g;
                bf[ni][0] = BS(buf, kt + t,     n) + 0x1000u;
                bf[ni][1] = BS(buf, kt + t + 4, n) + 0x1000u;
            }
            #pragma unroll
            for (int mi = 0; mi < 4; ++mi)
                #pragma unroll
                for (int ni = 0; ni < 4; ++ni)
                    mma_tf32(acc[mi][ni], af[mi][0], af[mi][1], af[mi][2], af[mi][3],
                             bf[ni][0], bf[ni][1]);
        }
    }

    // epilogue: bias (+residual) (+rope)
    #pragma unroll
    for (int mi = 0; mi < 4; ++mi) {
        int r_top = row0 + wm + mi * 16 + g;
        int r_bot = r_top + 8;
        #pragma unroll
        for (int ni = 0; ni < 4; ++ni) {
            int c = col0 + wn + ni * 8 + 2 * t;   // even column
            float bx = bias[c], by = bias[c + 1];
            float2 w0 = make_float2(acc[mi][ni][0] + bx, acc[mi][ni][1] + by);
            float2 w1 = make_float2(acc[mi][ni][2] + bx, acc[mi][ni][3] + by);
            if (RES) {
                float2 r0 = *(const float2*)(res + (size_t)r_top * Nn + c);
                float2 r1 = *(const float2*)(res + (size_t)r_bot * Nn + c);
                w0.x += r0.x; w0.y += r0.y;
                w1.x += r1.x; w1.y += r1.y;
            }
            if (ROPE && c < 2048) {            // q,k columns get rope
                int i = (c & 63) >> 1;
                float2 cs0 = rtab[(r_top & 2047) * 32 + i];
                float2 cs1 = rtab[(r_bot & 2047) * 32 + i];
                float a0 = w0.x, a1 = w0.y;
                w0.x = a0 * cs0.x - a1 * cs0.y;
                w0.y = a1 * cs0.x + a0 * cs0.y;
                a0 = w1.x; a1 = w1.y;
                w1.x = a0 * cs1.x - a1 * cs1.y;
                w1.y = a1 * cs1.x + a0 * cs1.y;
            }
            *(float2*)(C + (size_t)r_top * Nn + c) = w0;
            *(float2*)(C + (size_t)r_bot * Nn + c) = w1;
        }
    }
}

// ---------------- tensor-core flash attention -------------------------------
#define QP_STR 68
#define KS_STR 68
#define VS_STR 72

__global__ __launch_bounds__(128) void k_attn(const float* __restrict__ qkv,
                                              float* __restrict__ out) {
    extern __shared__ float sm[];
    float* QP = sm;
    float* Ks = sm + 64 * QP_STR;
    float* Vs = sm + 64 * (QP_STR + KS_STR);

    const int tid  = threadIdx.x;
    const int lane = tid & 31;
    const int g    = lane >> 2;
    const int t    = lane & 3;
    const int warp = tid >> 5;
    const int m0   = warp * 16;

    const int qt = blockIdx.x, bh = blockIdx.y;
    const int b = bh >> 4, h = bh & 15;
    const int base_tok = b * 2048;

    #pragma unroll
    for (int f = tid; f < 1024; f += 128) {
        int row = f >> 4, dc = (f & 15) << 2;
        int tok = base_tok + qt * 64 + row;
        float4 q4 = *(const float4*)(qkv + (size_t)tok * 3072 + h * 64 + dc);
        uint4 u;
        u.x = cvt_tf32(q4.x * 0.125f); u.y = cvt_tf32(q4.y * 0.125f);
        u.z = cvt_tf32(q4.z * 0.125f); u.w = cvt_tf32(q4.w * 0.125f);
        *(uint4*)(QP + row * QP_STR + dc) = u;
    }
    __syncthreads();

    unsigned qa[8][4];
    #pragma unroll
    for (int ks = 0; ks < 8; ++ks) {
        const unsigned* q0 = (const unsigned*)(QP + (m0 + g) * QP_STR);
        const unsigned* q1 = (const unsigned*)(QP + (m0 + g + 8) * QP_STR);
        qa[ks][0] = q0[ks * 8 + t];
        qa[ks][1] = q1[ks * 8 + t];
        qa[ks][2] = q0[ks * 8 + t + 4];
        qa[ks][3] = q1[ks * 8 + t + 4];
    }

    float o[8][4];
    #pragma unroll
    for (int j = 0; j < 8; ++j)
        #pragma unroll
        for (int r = 0; r < 4; ++r) o[j][r] = 0.f;
    float M1 = -INFINITY, M2 = -INFINITY, L1 = 0.f, L2 = 0.f;

    for (int kt = 0; kt < 32; ++kt) {
        __syncthreads();
        #pragma unroll
        for (int f = tid; f < 1024; f += 128) {
            int row = f >> 4, dc = (f & 15) << 2;
            int tok = base_tok + kt * 64 + row;
            float4 k4 = *(const float4*)(qkv + (size_t)tok * 3072 + 1024 + h * 64 + dc);
            uint4 u;
            u.x = cvt_tf32(k4.x); u.y = cvt_tf32(k4.y);
            u.z = cvt_tf32(k4.z); u.w = cvt_tf32(k4.w);
            *(uint4*)(Ks + row * KS_STR + dc) = u;
            float4 v4 = *(const float4*)(qkv + (size_t)tok * 3072 + 2048 + h * 64 + dc);
            u.x = cvt_tf32(v4.x); u.y = cvt_tf32(v4.y);
            u.z = cvt_tf32(v4.z); u.w = cvt_tf32(v4.w);
            *(uint4*)(Vs + row * VS_STR + dc) = u;
        }
        __syncthreads();

        float s[8][4];
        #pragma unroll
        for (int j = 0; j < 8; ++j)
            #pragma unroll
            for (int r = 0; r < 4; ++r) s[j][r] = 0.f;

        #pragma unroll
        for (int ks = 0; ks < 8; ++ks) {
            unsigned kb[8][2];
            #pragma unroll
            for (int j = 0; j < 8; ++j) {
                const unsigned* kr = (const unsigned*)(Ks + (j * 8 + g) * KS_STR);
                kb[j][0] = kr[ks * 8 + t];
                kb[j][1] = kr[ks * 8 + t + 4];
            }
            #pragma unroll
            for (int j = 0; j < 8; ++j)
                mma_tf32(s[j], qa[ks][0], qa[ks][1], qa[ks][2], qa[ks][3],
                         kb[j][0], kb[j][1]);
        }

        float mx1 = -INFINITY, mx2 = -INFINITY;
        #pragma unroll
        for (int j = 0; j < 8; ++j) {
            mx1 = fmaxf(mx1, fmaxf(s[j][0], s[j][1]));
            mx2 = fmaxf(mx2, fmaxf(s[j][2], s[j][3]));
        }
        mx1 = fmaxf(mx1, __shfl_xor_sync(0xFFFFFFFFu, mx1, 1));
        mx1 = fmaxf(mx1, __shfl_xor_sync(0xFFFFFFFFu, mx1, 2));
        mx2 = fmaxf(mx2, __shfl_xor_sync(0xFFFFFFFFu, mx2, 1));
        mx2 = fmaxf(mx2, __shfl_xor_sync(0xFFFFFFFFu, mx2, 2));
        float mn1 = fmaxf(M1, mx1), mn2 = fmaxf(M2, mx2);
        float cr1 = __expf(M1 - mn1), cr2 = __expf(M2 - mn2);
        float l1 = 0.f, l2 = 0.f;
        #pragma unroll
        for (int j = 0; j < 8; ++j) {
            s[j][0] = __expf(s[j][0] - mn1);
            s[j][1] = __expf(s[j][1] - mn1);
            s[j][2] = __expf(s[j][2] - mn2);
            s[j][3] = __expf(s[j][3] - mn2);
            l1 += s[j][0] + s[j][1];
            l2 += s[j][2] + s[j][3];
        }
        l1 += __shfl_xor_sync(0xFFFFFFFFu, l1, 1);
        l1 += __shfl_xor_sync(0xFFFFFFFFu, l1, 2);
        l2 += __shfl_xor_sync(0xFFFFFFFFu, l2, 1);
        l2 += __shfl_xor_sync(0xFFFFFFFFu, l2, 2);
        L1 = L1 * cr1 + l1;  M1 = mn1;
        L2 = L2 * cr2 + l2;  M2 = mn2;
        #pragma unroll
        for (int j = 0; j < 8; ++j) {
            o[j][0] *= cr1; o[j][1] *= cr1;
            o[j][2] *= cr2; o[j][3] *= cr2;
        }

        #pragma unroll
        for (int j = 0; j < 8; ++j) {
            unsigned* p0 = (unsigned*)(QP + (m0 + g) * QP_STR);
            unsigned* p1 = (unsigned*)(QP + (m0 + g + 8) * QP_STR);
            p0[j * 8 + 2 * t]     = cvt_tf32(s[j][0]);
            p0[j * 8 + 2 * t + 1] = cvt_tf32(s[j][1]);
            p1[j * 8 + 2 * t]     = cvt_tf32(s[j][2]);
            p1[j * 8 + 2 * t + 1] = cvt_tf32(s[j][3]);
        }
        __syncwarp();

        #pragma unroll
        for (int ks = 0; ks < 8; ++ks) {
            const unsigned* p0 = (const unsigned*)(QP + (m0 + g) * QP_STR);
            const unsigned* p1 = (const unsigned*)(QP + (m0 + g + 8) * QP_STR);
            unsigned pa0 = p0[ks * 8 + t];
            unsigned pa1 = p1[ks * 8 + t];
            unsigned pa2 = p0[ks * 8 + t + 4];
            unsigned pa3 = p1[ks * 8 + t + 4];
            #pragma unroll
            for (int j = 0; j < 8; ++j) {
                const unsigned* vr  = (const unsigned*)(Vs + (ks * 8 + t) * VS_STR);
                const unsigned* vr4 = (const unsigned*)(Vs + (ks * 8 + t + 4) * VS_STR);
                unsigned vb0 = vr[j * 8 + g];
                unsigned vb1 = vr4[j * 8 + g];
                mma_tf32(o[j], pa0, pa1, pa2, pa3, vb0, vb1);
            }
        }
    }

    float r1 = 1.f / L1, r2 = 1.f / L2;
    int row1 = base_tok + qt * 64 + m0 + g;
    int row2 = row1 + 8;
    #pragma unroll
    for (int j = 0; j < 8; ++j) {
        int c = h * 64 + j * 8 + 2 * t;
        *(float2*)(out + (size_t)row1 * 1024 + c) = make_float2(o[j][0] * r1, o[j][1] * r1);
        *(float2*)(out + (size_t)row2 * 1024 + c) = make_float2(o[j][2] * r2, o[j][3] * r2);
    }
}

// ---------------- SwiGLU for FFN -------------------------------------------
__global__ void k_swiglu(const float* __restrict__ u, float* __restrict__ s) {
    int idx = blockIdx.x * 256 + threadIdx.x;
    int m = idx >> 10, c4 = (idx & 1023) << 2;
    float4 a = *(const float4*)(u + (size_t)m * 8192 + c4);
    float4 g = *(const float4*)(u + (size_t)m * 8192 + 4096 + c4);
    float4 o;
    o.x = a.x * (g.x / (1.f + __expf(-g.x)));
    o.y = a.y * (g.y / (1.f + __expf(-g.y)));
    o.z = a.z * (g.z / (1.f + __expf(-g.z)));
    o.w = a.w * (g.w / (1.f + __expf(-g.w)));
    *(float4*)(s + (size_t)m * 4096 + c4) = o;
}

// ---------------- launcher --------------------------------------------------
extern "C" void kernel_launch(void* const* d_in, const int* in_sizes, int n_in,
                              void* d_out, int out_size) {
    const float* x     = (const float*)d_in[0];
    const float* temb  = (const float*)d_in[1];
    const float* g1    = (const float*)d_in[2];
    const float* g2    = (const float*)d_in[3];
    const float* w_qkv = (const float*)d_in[4];
    const float* b_qkv = (const float*)d_in[5];
    const float* w_ao  = (const float*)d_in[6];
    const float* b_ao  = (const float*)d_in[7];
    const float* w_fc  = (const float*)d_in[8];
    const float* b_fc  = (const float*)d_in[9];
    const float* w_fo  = (const float*)d_in[10];
    const float* b_fo  = (const float*)d_in[11];
    const float* w_t1  = (const float*)d_in[12];
    const float* b_t1  = (const float*)d_in[13];
    const float* w_t2  = (const float*)d_in[14];
    const float* b_t2  = (const float*)d_in[15];
    float* out = (float*)d_out;

    float *tpu, *tps, *tp, *part, *h, *qkv, *att, *x1, *u, *sw;
    float2* rtab;
    cudaGetSymbolAddress((void**)&tpu,  g_tpu);
    cudaGetSymbolAddress((void**)&tps,  g_tps);
    cudaGetSymbolAddress((void**)&tp,   g_tp);
    cudaGetSymbolAddress((void**)&part, g_part);
    cudaGetSymbolAddress((void**)&h,    g_h);
    cudaGetSymbolAddress((void**)&qkv,  g_qkv);
    cudaGetSymbolAddress((void**)&att,  g_att);
    cudaGetSymbolAddress((void**)&x1,   g_x1);
    cudaGetSymbolAddress((void**)&u,    g_u);
    cudaGetSymbolAddress((void**)&sw,   g_sw);
    cudaGetSymbolAddress((void**)&rtab, g_ropetab);

    const int attn_smem = 64 * (QP_STR + KS_STR + VS_STR) * 4;
    cudaFuncSetAttribute(k_attn, cudaFuncAttributeMaxDynamicSharedMemorySize, attn_smem);
    cudaFuncSetAttribute(k_tgemm<false, true>,  cudaFuncAttributeMaxDynamicSharedMemorySize, GEMM_SMEM);
    cudaFuncSetAttribute(k_tgemm<true, false>,  cudaFuncAttributeMaxDynamicSharedMemorySize, GEMM_SMEM);
    cudaFuncSetAttribute(k_tgemm<false, false>, cudaFuncAttributeMaxDynamicSharedMemorySize, GEMM_SMEM);

    // rope table + time-conditioning MLP (split-K, deterministic)
    k_ropetab<<<256, 256>>>(rtab);
    k_tpart<<<dim3(16, 2, 8), 128>>>(temb, w_t1, part, 1024, 2048);
    k_treduce<<<dim3(8, 2), 256>>>(part, b_t1, tpu, 2048);
    k_tswiglu<<<8, 256>>>(tpu, tps);
    k_tpart<<<dim3(32, 2, 8), 128>>>(tps, w_t2, part, 1024, 4096);
    k_treduce<<<dim3(16, 2), 256>>>(part, b_t2, tp, 4096);

    // attention branch
    k_rmsnorm<<<4096, 256>>>(x, g1, tp, 0, 1024, h);
    k_tgemm<false, true><<<dim3(24, 32), 256, GEMM_SMEM>>>(h, w_qkv, b_qkv, nullptr, rtab, qkv, 3072, 1024);
    k_attn<<<dim3(32, 32), 128, attn_smem>>>(qkv, att);
    k_tgemm<true, false><<<dim3(8, 32), 256, GEMM_SMEM>>>(att, w_ao, b_ao, x, rtab, x1, 1024, 1024);

    // FFN branch
    k_rmsnorm<<<4096, 256>>>(x1, g2, tp, 2048, 3072, h);
    k_tgemm<false, false><<<dim3(64, 32), 256, GEMM_SMEM>>>(h, w_fc, b_fc, nullptr, rtab, u, 8192, 1024);
    k_swiglu<<<16384, 256>>>(u, sw);
    k_tgemm<true, false><<<dim3(8, 32), 256, GEMM_SMEM>>>(sw, w_fo, b_fo, x1, rtab, out, 1024, 4096);
}

// round 8
// speedup vs baseline: 4.2548x; 1.0149x over previous
#include <cuda_runtime.h>
#include <math.h>

// Problem constants: B=2, T=2048, D=1024, H=16, hd=64, M = B*T = 4096
#define MROWS 4096

// ---------------- scratch (device globals; no allocation allowed) ----------
__device__ float g_tpu [2 * 2048];       // time MLP hidden
__device__ float g_tps [2 * 1024];       // time MLP after swiglu
__device__ float g_tp  [2 * 4096];       // shift1|scale1|shift2|scale2
__device__ float g_part[8 * 2 * 4096];   // split-K partials for time MLP
__device__ float g_h   [MROWS * 1024];   // normed/modulated activations
__device__ float g_qkv [MROWS * 3072];   // qkv projections (rope fused)
__device__ float g_att [MROWS * 1024];   // attention output (b,t,h,d)
__device__ float g_x1  [MROWS * 1024];   // x after attention residual
__device__ float g_u   [MROWS * 8192];   // ffn pre-activation
__device__ float g_sw  [MROWS * 4096];   // ffn post-swiglu
__device__ float2 g_ropetab[2048 * 32];  // (cos, sin) per (pos, pair)

__device__ __forceinline__ unsigned cvt_tf32(float f) {
    unsigned u;
    asm("cvt.rna.tf32.f32 %0, %1;" : "=r"(u) : "f"(f));
    return u;
}

__device__ __forceinline__ void mma_tf32(float* c, unsigned a0, unsigned a1,
                                         unsigned a2, unsigned a3,
                                         unsigned b0, unsigned b1) {
    asm volatile(
        "mma.sync.aligned.m16n8k8.row.col.f32.tf32.tf32.f32 "
        "{%0,%1,%2,%3}, {%4,%5,%6,%7}, {%8,%9}, {%0,%1,%2,%3};\n"
        : "+f"(c[0]), "+f"(c[1]), "+f"(c[2]), "+f"(c[3])
        : "r"(a0), "r"(a1), "r"(a2), "r"(a3), "r"(b0), "r"(b1));
}

__device__ __forceinline__ void ldsm4(unsigned& r0, unsigned& r1,
                                      unsigned& r2, unsigned& r3, unsigned addr) {
    asm volatile("ldmatrix.sync.aligned.m8n8.x4.shared.b16 {%0,%1,%2,%3}, [%4];"
                 : "=r"(r0), "=r"(r1), "=r"(r2), "=r"(r3) : "r"(addr));
}

__device__ __forceinline__ void cp16(void* dst, const void* src) {
    unsigned ds = (unsigned)__cvta_generic_to_shared(dst);
    asm volatile("cp.async.cg.shared.global [%0], [%1], 16;\n" :: "r"(ds), "l"(src));
}
__device__ __forceinline__ void cp_commit() {
    asm volatile("cp.async.commit_group;\n");
}
template <int N>
__device__ __forceinline__ void cp_wait() {
    asm volatile("cp.async.wait_group %0;\n" :: "n"(N));
}

// ---------------- time-MLP: split-K partial GEMM + reduce -------------------
__global__ __launch_bounds__(128) void k_tpart(const float* __restrict__ in,
                                               const float* __restrict__ w,
                                               float* __restrict__ part,
                                               int K, int N) {
    int n = blockIdx.x * 128 + threadIdx.x;
    int b = blockIdx.y, s = blockIdx.z;
    const float* xr = in + b * K + s * 128;
    const float* wp = w + (size_t)(s * 128) * N + n;
    float acc = 0.f;
    #pragma unroll 8
    for (int k = 0; k < 128; ++k) acc += xr[k] * wp[(size_t)k * N];
    part[(s * 2 + b) * 4096 + n] = acc;
}

__global__ void k_treduce(const float* __restrict__ part,
                          const float* __restrict__ bias,
                          float* __restrict__ out, int N) {
    int n = blockIdx.x * 256 + threadIdx.x;
    int b = blockIdx.y;
    if (n >= N) return;
    float acc = bias[n];
    #pragma unroll
    for (int s = 0; s < 8; ++s) acc += part[(s * 2 + b) * 4096 + n];
    out[b * N + n] = acc;
}

__global__ void k_tswiglu(const float* __restrict__ u, float* __restrict__ s) {
    int i = blockIdx.x * 256 + threadIdx.x;  // 2048 total
    if (i >= 2048) return;
    int b = i >> 10, j = i & 1023;
    float a = u[b * 2048 + j];
    float g = u[b * 2048 + 1024 + j];
    s[b * 1024 + j] = a * (g / (1.f + expf(-g)));
}

// ---------------- rope cos/sin table ---------------------------------------
__global__ void k_ropetab(float2* __restrict__ tab) {
    int idx = blockIdx.x * 256 + threadIdx.x;   // 65536
    int t = idx >> 5, i = idx & 31;
    float inv = powf(10000.f, -(float)i * (1.f / 32.f));
    float sn, cs;
    sincosf((float)t * inv, &sn, &cs);
    tab[idx] = make_float2(cs, sn);
}

// ---------------- fused RMSNorm + adaLN modulation --------------------------
__global__ __launch_bounds__(256) void k_rmsnorm(const float* __restrict__ x,
                                                 const float* __restrict__ g,
                                                 const float* __restrict__ tp,
                                                 int shift_off, int scale_off,
                                                 float* __restrict__ out) {
    int row = blockIdx.x;          // 0..4095
    int b   = row >> 11;
    const float4* xr = (const float4*)(x + row * 1024);
    float4 v = xr[threadIdx.x];
    float ss = v.x * v.x + v.y * v.y + v.z * v.z + v.w * v.w;
    #pragma unroll
    for (int off = 16; off; off >>= 1) ss += __shfl_xor_sync(0xFFFFFFFFu, ss, off);
    __shared__ float wsum[8];
    __shared__ float stot;
    if ((threadIdx.x & 31) == 0) wsum[threadIdx.x >> 5] = ss;
    __syncthreads();
    if (threadIdx.x == 0) {
        float t = 0.f;
        #pragma unroll
        for (int i = 0; i < 8; ++i) t += wsum[i];
        stot = rsqrtf(t * (1.f / 1024.f) + 1.1920928955078125e-7f);
    }
    __syncthreads();
    float r = stot;
    int j = threadIdx.x * 4;
    const float* gg = g + j;
    const float* sc = tp + b * 4096 + scale_off + j;
    const float* sh = tp + b * 4096 + shift_off + j;
    float4 o;
    o.x = v.x * r * gg[0] * (1.f + sc[0]) + sh[0];
    o.y = v.y * r * gg[1] * (1.f + sc[1]) + sh[1];
    o.z = v.z * r * gg[2] * (1.f + sc[2]) + sh[2];
    o.w = v.w * r * gg[3] * (1.f + sc[3]) + sh[3];
    ((float4*)(out + row * 1024))[threadIdx.x] = o;
}

// ---------------- tf32 tensor-core GEMM, 3-stage cp.async + ldmatrix --------
#define AS(s, m, k) Asm[((s) * 128 + (m)) * 20 + (k)]
#define BS(s, r, n) Bsm[((s) * 16 + (r)) * 136 + (n)]
#define GEMM_SMEM ((3 * 128 * 20 + 3 * 16 * 136) * 4)

template <bool RES, bool ROPE>
__global__ __launch_bounds__(256) void k_tgemm(const float* __restrict__ A,
                                               const float* __restrict__ B,
                                               const float* __restrict__ bias,
                                               const float* __restrict__ res,
                                               const float2* __restrict__ rtab,
                                               float* __restrict__ C,
                                               int Nn, int Kn) {
    extern __shared__ unsigned smemraw[];
    unsigned* Asm = smemraw;                    // [3][128][20]
    unsigned* Bsm = smemraw + 3 * 128 * 20;     // [3][16][136]
    const unsigned As_u32 = (unsigned)__cvta_generic_to_shared(Asm);

    const int tid  = threadIdx.x;
    const int lane = tid & 31;
    const int g    = lane >> 2;
    const int t    = lane & 3;
    const int warp = tid >> 5;
    const int wm   = (warp >> 2) * 64;
    const int wn   = (warp & 3) * 32;

    // ldmatrix per-lane source mapping: rows lane&15, col block by lane>>4
    const int lm_row = lane & 15;
    const int lm_k   = (lane >> 4) << 2;

    const int row0 = blockIdx.y * 128;
    const int col0 = blockIdx.x * 128;

    const int arow = tid >> 2;         // 0..63 (+64)
    const int ac4  = tid & 3;
    const int brow = tid >> 5;         // 0..7 (+8)
    const int bc4  = tid & 31;

    const float* Ap0 = A + (size_t)(row0 + arow)      * Kn + ac4 * 4;
    const float* Ap1 = A + (size_t)(row0 + arow + 64) * Kn + ac4 * 4;
    const float* Bp0 = B + (size_t)brow       * Nn + col0 + bc4 * 4;
    const float* Bp1 = B + (size_t)(brow + 8) * Nn + col0 + bc4 * 4;

    float acc[4][4][4];
    #pragma unroll
    for (int mi = 0; mi < 4; ++mi)
        #pragma unroll
        for (int ni = 0; ni < 4; ++ni)
            #pragma unroll
            for (int r = 0; r < 4; ++r) acc[mi][ni][r] = 0.f;

    const int tiles = Kn >> 4;

    #pragma unroll
    for (int s = 0; s < 2; ++s) {
        cp16(&AS(s, arow, ac4 * 4),      Ap0);
        cp16(&AS(s, arow + 64, ac4 * 4), Ap1);
        cp16(&BS(s, brow, bc4 * 4),      Bp0);
        cp16(&BS(s, brow + 8, bc4 * 4),  Bp1);
        cp_commit();
        Ap0 += 16; Ap1 += 16;
        Bp0 += (size_t)16 * Nn; Bp1 += (size_t)16 * Nn;
    }

    for (int i = 0; i < tiles; ++i) {
        const int buf = i % 3;
        cp_wait<1>();
        __syncthreads();
        if (i + 2 < tiles) {
            const int nb = (i + 2) % 3;
            cp16(&AS(nb, arow, ac4 * 4),      Ap0);
            cp16(&AS(nb, arow + 64, ac4 * 4), Ap1);
            cp16(&BS(nb, brow, bc4 * 4),      Bp0);
            cp16(&BS(nb, brow + 8, bc4 * 4),  Bp1);
            Ap0 += 16; Ap1 += 16;
            Bp0 += (size_t)16 * Nn; Bp1 += (size_t)16 * Nn;
        }
        cp_commit();

        #pragma unroll
        for (int sub = 0; sub < 2; ++sub) {
            const int kt = sub * 8;
            unsigned af[4][4], bf[4][2];
            #pragma unroll
            for (int mi = 0; mi < 4; ++mi) {
                unsigned addr = As_u32 +
                    (((buf * 128 + wm + mi * 16 + lm_row) * 20) + kt + lm_k) * 4u;
                ldsm4(af[mi][0], af[mi][1], af[mi][2], af[mi][3], addr);
                af[mi][0] += 0x1000u; af[mi][1] += 0x1000u;
                af[mi][2] += 0x1000u; af[mi][3] += 0x1000u;
            }
            #pragma unroll
            for (int ni = 0; ni < 4; ++ni) {
                int n = wn + ni * 8 + g;
                bf[ni][0] = BS(buf, kt + t,     n) + 0x1000u;
                bf[ni][1] = BS(buf, kt + t + 4, n) + 0x1000u;
            }
            #pragma unroll
            for (int mi = 0; mi < 4; ++mi)
                #pragma unroll
                for (int ni = 0; ni < 4; ++ni)
                    mma_tf32(acc[mi][ni], af[mi][0], af[mi][1], af[mi][2], af[mi][3],
                             bf[ni][0], bf[ni][1]);
        }
    }

    #pragma unroll
    for (int mi = 0; mi < 4; ++mi) {
        int r_top = row0 + wm + mi * 16 + g;
        int r_bot = r_top + 8;
        #pragma unroll
        for (int ni = 0; ni < 4; ++ni) {
            int c = col0 + wn + ni * 8 + 2 * t;   // even column
            float bx = bias[c], by = bias[c + 1];
            float2 w0 = make_float2(acc[mi][ni][0] + bx, acc[mi][ni][1] + by);
            float2 w1 = make_float2(acc[mi][ni][2] + bx, acc[mi][ni][3] + by);
            if (RES) {
                float2 r0 = *(const float2*)(res + (size_t)r_top * Nn + c);
                float2 r1 = *(const float2*)(res + (size_t)r_bot * Nn + c);
                w0.x += r0.x; w0.y += r0.y;
                w1.x += r1.x; w1.y += r1.y;
            }
            if (ROPE && c < 2048) {            // q,k columns get rope
                int i = (c & 63) >> 1;
                float2 cs0 = rtab[(r_top & 2047) * 32 + i];
                float2 cs1 = rtab[(r_bot & 2047) * 32 + i];
                float a0 = w0.x, a1 = w0.y;
                w0.x = a0 * cs0.x - a1 * cs0.y;
                w0.y = a1 * cs0.x + a0 * cs0.y;
                a0 = w1.x; a1 = w1.y;
                w1.x = a0 * cs1.x - a1 * cs1.y;
                w1.y = a1 * cs1.x + a0 * cs1.y;
            }
            *(float2*)(C + (size_t)r_top * Nn + c) = w0;
            *(float2*)(C + (size_t)r_bot * Nn + c) = w1;
        }
    }
}

// ---------------- tensor-core flash attention, cp.async K/V pipeline --------
#define QP_STR 68
#define KS_STR 68
#define VS_STR 72
#define ATTN_SMEM (64 * (QP_STR + 2 * KS_STR + 2 * VS_STR) * 4)

__global__ __launch_bounds__(128) void k_attn(const float* __restrict__ qkv,
                                              float* __restrict__ out) {
    extern __shared__ float sm[];
    float* QP = sm;                                   // 64*68
    float* Ks = sm + 64 * QP_STR;                     // 2 x 64*68
    float* Vs = sm + 64 * (QP_STR + 2 * KS_STR);      // 2 x 64*72

    const int tid  = threadIdx.x;
    const int lane = tid & 31;
    const int g    = lane >> 2;
    const int t    = lane & 3;
    const int warp = tid >> 5;
    const int m0   = warp * 16;

    const int qt = blockIdx.x, bh = blockIdx.y;
    const int b = bh >> 4, h = bh & 15;
    const int base_tok = b * 2048;

    const int ld_row = tid >> 4;            // 0..7 (each thread: 8 rows, stride 8)
    const int ld_dc  = (tid & 15) << 2;

    // prologue: cp.async K/V tile 0 into buffer 0
    #pragma unroll
    for (int rr = 0; rr < 8; ++rr) {
        int row = ld_row + rr * 8;
        int tok = base_tok + row;           // kt = 0
        cp16(Ks + row * KS_STR + ld_dc, qkv + (size_t)tok * 3072 + 1024 + h * 64 + ld_dc);
        cp16(Vs + row * VS_STR + ld_dc, qkv + (size_t)tok * 3072 + 2048 + h * 64 + ld_dc);
    }
    cp_commit();

    // load Q tile (scaled, tf32-rounded) while tile 0 is in flight
    #pragma unroll
    for (int f = tid; f < 1024; f += 128) {
        int row = f >> 4, dc = (f & 15) << 2;
        int tok = base_tok + qt * 64 + row;
        float4 q4 = *(const float4*)(qkv + (size_t)tok * 3072 + h * 64 + dc);
        uint4 u;
        u.x = cvt_tf32(q4.x * 0.125f); u.y = cvt_tf32(q4.y * 0.125f);
        u.z = cvt_tf32(q4.z * 0.125f); u.w = cvt_tf32(q4.w * 0.125f);
        *(uint4*)(QP + row * QP_STR + dc) = u;
    }
    __syncthreads();

    unsigned qa[8][4];
    #pragma unroll
    for (int ks = 0; ks < 8; ++ks) {
        const unsigned* q0 = (const unsigned*)(QP + (m0 + g) * QP_STR);
        const unsigned* q1 = (const unsigned*)(QP + (m0 + g + 8) * QP_STR);
        qa[ks][0] = q0[ks * 8 + t];
        qa[ks][1] = q1[ks * 8 + t];
        qa[ks][2] = q0[ks * 8 + t + 4];
        qa[ks][3] = q1[ks * 8 + t + 4];
    }

    float o[8][4];
    #pragma unroll
    for (int j = 0; j < 8; ++j)
        #pragma unroll
        for (int r = 0; r < 4; ++r) o[j][r] = 0.f;
    float M1 = -INFINITY, M2 = -INFINITY, L1 = 0.f, L2 = 0.f;

    for (int kt = 0; kt < 32; ++kt) {
        const int buf = kt & 1;
        float* Kb = Ks + buf * 64 * KS_STR;
        float* Vb = Vs + buf * 64 * VS_STR;

        __syncthreads();   // all threads done computing on the other buffer
        if (kt + 1 < 32) {
            float* Kn = Ks + (buf ^ 1) * 64 * KS_STR;
            float* Vn = Vs + (buf ^ 1) * 64 * VS_STR;
            #pragma unroll
            for (int rr = 0; rr < 8; ++rr) {
                int row = ld_row + rr * 8;
                int tok = base_tok + (kt + 1) * 64 + row;
                cp16(Kn + row * KS_STR + ld_dc, qkv + (size_t)tok * 3072 + 1024 + h * 64 + ld_dc);
                cp16(Vn + row * VS_STR + ld_dc, qkv + (size_t)tok * 3072 + 2048 + h * 64 + ld_dc);
            }
        }
        cp_commit();
        cp_wait<1>();      // current tile kt complete
        __syncthreads();

        // ---- S = Q K^T ------------------------------------------------------
        float s[8][4];
        #pragma unroll
        for (int j = 0; j < 8; ++j)
            #pragma unroll
            for (int r = 0; r < 4; ++r) s[j][r] = 0.f;

        #pragma unroll
        for (int ks = 0; ks < 8; ++ks) {
            unsigned kb[8][2];
            #pragma unroll
            for (int j = 0; j < 8; ++j) {
                const unsigned* kr = (const unsigned*)(Kb + (j * 8 + g) * KS_STR);
                kb[j][0] = kr[ks * 8 + t]     + 0x1000u;
                kb[j][1] = kr[ks * 8 + t + 4] + 0x1000u;
            }
            #pragma unroll
            for (int j = 0; j < 8; ++j)
                mma_tf32(s[j], qa[ks][0], qa[ks][1], qa[ks][2], qa[ks][3],
                         kb[j][0], kb[j][1]);
        }

        // ---- online softmax -------------------------------------------------
        float mx1 = -INFINITY, mx2 = -INFINITY;
        #pragma unroll
        for (int j = 0; j < 8; ++j) {
            mx1 = fmaxf(mx1, fmaxf(s[j][0], s[j][1]));
            mx2 = fmaxf(mx2, fmaxf(s[j][2], s[j][3]));
        }
        mx1 = fmaxf(mx1, __shfl_xor_sync(0xFFFFFFFFu, mx1, 1));
        mx1 = fmaxf(mx1, __shfl_xor_sync(0xFFFFFFFFu, mx1, 2));
        mx2 = fmaxf(mx2, __shfl_xor_sync(0xFFFFFFFFu, mx2, 1));
        mx2 = fmaxf(mx2, __shfl_xor_sync(0xFFFFFFFFu, mx2, 2));
        float mn1 = fmaxf(M1, mx1), mn2 = fmaxf(M2, mx2);
        float cr1 = __expf(M1 - mn1), cr2 = __expf(M2 - mn2);
        float l1 = 0.f, l2 = 0.f;
        #pragma unroll
        for (int j = 0; j < 8; ++j) {
            s[j][0] = __expf(s[j][0] - mn1);
            s[j][1] = __expf(s[j][1] - mn1);
            s[j][2] = __expf(s[j][2] - mn2);
            s[j][3] = __expf(s[j][3] - mn2);
            l1 += s[j][0] + s[j][1];
            l2 += s[j][2] + s[j][3];
        }
        l1 += __shfl_xor_sync(0xFFFFFFFFu, l1, 1);
        l1 += __shfl_xor_sync(0xFFFFFFFFu, l1, 2);
        l2 += __shfl_xor_sync(0xFFFFFFFFu, l2, 1);
        l2 += __shfl_xor_sync(0xFFFFFFFFu, l2, 2);
        L1 = L1 * cr1 + l1;  M1 = mn1;
        L2 = L2 * cr2 + l2;  M2 = mn2;
        #pragma unroll
        for (int j = 0; j < 8; ++j) {
            o[j][0] *= cr1; o[j][1] *= cr1;
            o[j][2] *= cr2; o[j][3] *= cr2;
        }

        // ---- P -> smem (own warp rows), PV mma ------------------------------
        #pragma unroll
        for (int j = 0; j < 8; ++j) {
            unsigned* p0 = (unsigned*)(QP + (m0 + g) * QP_STR);
            unsigned* p1 = (unsigned*)(QP + (m0 + g + 8) * QP_STR);
            p0[j * 8 + 2 * t]     = cvt_tf32(s[j][0]);
            p0[j * 8 + 2 * t + 1] = cvt_tf32(s[j][1]);
            p1[j * 8 + 2 * t]     = cvt_tf32(s[j][2]);
            p1[j * 8 + 2 * t + 1] = cvt_tf32(s[j][3]);
        }
        __syncwarp();

        #pragma unroll
        for (int ks = 0; ks < 8; ++ks) {
            const unsigned* p0 = (const unsigned*)(QP + (m0 + g) * QP_STR);
            const unsigned* p1 = (const unsigned*)(QP + (m0 + g + 8) * QP_STR);
            unsigned pa0 = p0[ks * 8 + t];
            unsigned pa1 = p1[ks * 8 + t];
            unsigned pa2 = p0[ks * 8 + t + 4];
            unsigned pa3 = p1[ks * 8 + t + 4];
            #pragma unroll
            for (int j = 0; j < 8; ++j) {
                const unsigned* vr  = (const unsigned*)(Vb + (ks * 8 + t) * VS_STR);
                const unsigned* vr4 = (const unsigned*)(Vb + (ks * 8 + t + 4) * VS_STR);
                unsigned vb0 = vr[j * 8 + g]  + 0x1000u;
                unsigned vb1 = vr4[j * 8 + g] + 0x1000u;
                mma_tf32(o[j], pa0, pa1, pa2, pa3, vb0, vb1);
            }
        }
    }

    float r1 = 1.f / L1, r2 = 1.f / L2;
    int row1 = base_tok + qt * 64 + m0 + g;
    int row2 = row1 + 8;
    #pragma unroll
    for (int j = 0; j < 8; ++j) {
        int c = h * 64 + j * 8 + 2 * t;
        *(float2*)(out + (size_t)row1 * 1024 + c) = make_float2(o[j][0] * r1, o[j][1] * r1);
        *(float2*)(out + (size_t)row2 * 1024 + c) = make_float2(o[j][2] * r2, o[j][3] * r2);
    }
}

// ---------------- SwiGLU for FFN -------------------------------------------
__global__ void k_swiglu(const float* __restrict__ u, float* __restrict__ s) {
    int idx = blockIdx.x * 256 + threadIdx.x;
    int m = idx >> 10, c4 = (idx & 1023) << 2;
    float4 a = *(const float4*)(u + (size_t)m * 8192 + c4);
    float4 g = *(const float4*)(u + (size_t)m * 8192 + 4096 + c4);
    float4 o;
    o.x = a.x * (g.x / (1.f + __expf(-g.x)));
    o.y = a.y * (g.y / (1.f + __expf(-g.y)));
    o.z = a.z * (g.z / (1.f + __expf(-g.z)));
    o.w = a.w * (g.w / (1.f + __expf(-g.w)));
    *(float4*)(s + (size_t)m * 4096 + c4) = o;
}

// ---------------- launcher --------------------------------------------------
extern "C" void kernel_launch(void* const* d_in, const int* in_sizes, int n_in,
                              void* d_out, int out_size) {
    const float* x     = (const float*)d_in[0];
    const float* temb  = (const float*)d_in[1];
    const float* g1    = (const float*)d_in[2];
    const float* g2    = (const float*)d_in[3];
    const float* w_qkv = (const float*)d_in[4];
    const float* b_qkv = (const float*)d_in[5];
    const float* w_ao  = (const float*)d_in[6];
    const float* b_ao  = (const float*)d_in[7];
    const float* w_fc  = (const float*)d_in[8];
    const float* b_fc  = (const float*)d_in[9];
    const float* w_fo  = (const float*)d_in[10];
    const float* b_fo  = (const float*)d_in[11];
    const float* w_t1  = (const float*)d_in[12];
    const float* b_t1  = (const float*)d_in[13];
    const float* w_t2  = (const float*)d_in[14];
    const float* b_t2  = (const float*)d_in[15];
    float* out = (float*)d_out;

    float *tpu, *tps, *tp, *part, *h, *qkv, *att, *x1, *u, *sw;
    float2* rtab;
    cudaGetSymbolAddress((void**)&tpu,  g_tpu);
    cudaGetSymbolAddress((void**)&tps,  g_tps);
    cudaGetSymbolAddress((void**)&tp,   g_tp);
    cudaGetSymbolAddress((void**)&part, g_part);
    cudaGetSymbolAddress((void**)&h,    g_h);
    cudaGetSymbolAddress((void**)&qkv,  g_qkv);
    cudaGetSymbolAddress((void**)&att,  g_att);
    cudaGetSymbolAddress((void**)&x1,   g_x1);
    cudaGetSymbolAddress((void**)&u,    g_u);
    cudaGetSymbolAddress((void**)&sw,   g_sw);
    cudaGetSymbolAddress((void**)&rtab, g_ropetab);

    cudaFuncSetAttribute(k_attn, cudaFuncAttributeMaxDynamicSharedMemorySize, ATTN_SMEM);
    cudaFuncSetAttribute(k_tgemm<false, true>,  cudaFuncAttributeMaxDynamicSharedMemorySize, GEMM_SMEM);
    cudaFuncSetAttribute(k_tgemm<true, false>,  cudaFuncAttributeMaxDynamicSharedMemorySize, GEMM_SMEM);
    cudaFuncSetAttribute(k_tgemm<false, false>, cudaFuncAttributeMaxDynamicSharedMemorySize, GEMM_SMEM);

    // rope table + time-conditioning MLP (split-K, deterministic)
    k_ropetab<<<256, 256>>>(rtab);
    k_tpart<<<dim3(16, 2, 8), 128>>>(temb, w_t1, part, 1024, 2048);
    k_treduce<<<dim3(8, 2), 256>>>(part, b_t1, tpu, 2048);
    k_tswiglu<<<8, 256>>>(tpu, tps);
    k_tpart<<<dim3(32, 2, 8), 128>>>(tps, w_t2, part, 1024, 4096);
    k_treduce<<<dim3(16, 2), 256>>>(part, b_t2, tp, 4096);

    // attention branch
    k_rmsnorm<<<4096, 256>>>(x, g1, tp, 0, 1024, h);
    k_tgemm<false, true><<<dim3(24, 32), 256, GEMM_SMEM>>>(h, w_qkv, b_qkv, nullptr, rtab, qkv, 3072, 1024);
    k_attn<<<dim3(32, 32), 128, ATTN_SMEM>>>(qkv, att);
    k_tgemm<true, false><<<dim3(8, 32), 256, GEMM_SMEM>>>(att, w_ao, b_ao, x, rtab, x1, 1024, 1024);

    // FFN branch
    k_rmsnorm<<<4096, 256>>>(x1, g2, tp, 2048, 3072, h);
    k_tgemm<false, false><<<dim3(64, 32), 256, GEMM_SMEM>>>(h, w_fc, b_fc, nullptr, rtab, u, 8192, 1024);
    k_swiglu<<<16384, 256>>>(u, sw);
    k_tgemm<true, false><<<dim3(8, 32), 256, GEMM_SMEM>>>(sw, w_fo, b_fo, x1, rtab, out, 1024, 4096);
}